// round 2
// baseline (speedup 1.0000x reference)
#include <cuda_runtime.h>

#define N_TOK   8192
#define DIM     1024
#define NEXP    8
#define HDIM    2048
#define CAP     8192     // worst-case tokens per expert (bucket capacity)
#define NSLOT   (N_TOK * 2)   // total assigned (token, slot) pairs = 16384

// -------- scratch (static device globals: no allocation allowed) ----------
__device__ int   g_counts[NEXP];
__device__ int   g_base[NEXP];                    // exclusive prefix of counts
__device__ int   g_tok[NEXP * CAP];               // packed token*2 + slot
__device__ float g_wt [NEXP * CAP];               // routing weight
__device__ float g_H  [(size_t)NSLOT * HDIM];     // 128 MB intermediate (compact)
__device__ float g_S  [(size_t)NSLOT * DIM];      // 64 MB per-slot outputs

// --------------------------------------------------------------------------
__global__ void zero_counts_kernel() {
    if (threadIdx.x < NEXP) g_counts[threadIdx.x] = 0;
}

// Tiny exclusive scan over 8 counts (single thread; negligible).
__global__ void scan_kernel() {
    if (threadIdx.x == 0) {
        int acc = 0;
#pragma unroll
        for (int e = 0; e < NEXP; e++) { g_base[e] = acc; acc += g_counts[e]; }
    }
}

// Router: one warp per token. Block stages router_w (8x1024 = 32KB) in smem.
__global__ __launch_bounds__(256) void router_kernel(
    const float* __restrict__ x, const float* __restrict__ rw)
{
    __shared__ float s_rw[NEXP * DIM];
    int tid = threadIdx.x;
    for (int i = tid; i < NEXP * DIM; i += 256) s_rw[i] = rw[i];
    __syncthreads();

    int warp = tid >> 5, lane = tid & 31;
    int t = blockIdx.x * 8 + warp;
    const float* xr = x + (size_t)t * DIM;

    float acc[NEXP];
#pragma unroll
    for (int e = 0; e < NEXP; e++) acc[e] = 0.0f;

    for (int j = lane; j < DIM; j += 32) {
        float xv = xr[j];
#pragma unroll
        for (int e = 0; e < NEXP; e++) acc[e] += xv * s_rw[e * DIM + j];
    }
#pragma unroll
    for (int e = 0; e < NEXP; e++) {
#pragma unroll
        for (int off = 16; off > 0; off >>= 1)
            acc[e] += __shfl_xor_sync(0xFFFFFFFFu, acc[e], off);
    }

    if (lane == 0) {
        // top-2 on logits (softmax is monotone; ties -> lowest index, like jax top_k)
        int e0 = 0; float l0 = acc[0];
#pragma unroll
        for (int e = 1; e < NEXP; e++) if (acc[e] > l0) { l0 = acc[e]; e0 = e; }
        int e1 = -1; float l1 = -3.0e38f;
#pragma unroll
        for (int e = 0; e < NEXP; e++)
            if (e != e0 && acc[e] > l1) { l1 = acc[e]; e1 = e; }
        // normalized top-2 softmax weights, computed pairwise (exact same value)
        float w0 = 1.0f / (1.0f + expf(l1 - l0));
        float w1 = 1.0f - w0;

        int p0 = atomicAdd(&g_counts[e0], 1);
        g_tok[e0 * CAP + p0] = t * 2;     g_wt[e0 * CAP + p0] = w0;
        int p1 = atomicAdd(&g_counts[e1], 1);
        g_tok[e1 * CAP + p1] = t * 2 + 1; g_wt[e1 * CAP + p1] = w1;
    }
}

// --------------------------------------------------------------------------
// GEMM1: per expert, C[m,n] = sum_k X[tok(m),k] * fc1[e][n][k]; h = relu(C)^2
// Tiles: 128x128, K-step 8, 256 threads, 8x8 register microtile.
__global__ __launch_bounds__(256) void gemm1_kernel(
    const float* __restrict__ x, const float* __restrict__ fc1)
{
    int e    = blockIdx.z;
    int n_e  = g_counts[e];
    int m0   = blockIdx.x * 128;
    if (m0 >= n_e) return;
    int base = g_base[e];
    int n0   = blockIdx.y * 128;

    __shared__ float As[8][128];
    __shared__ float Bs[8][128];

    int tid = threadIdx.x;
    int lr  = tid >> 1;          // row within 128-tile
    int lk  = (tid & 1) * 4;     // k offset 0 or 4

    int gm = m0 + lr;
    bool avalid = (gm < n_e);
    const float* aptr = nullptr;
    if (avalid) {
        int t = g_tok[e * CAP + gm] >> 1;
        aptr = x + (size_t)t * DIM + lk;
    }
    const float* bptr = fc1 + (size_t)e * HDIM * DIM + (size_t)(n0 + lr) * DIM + lk;

    int tx = tid & 15, ty = tid >> 4;

    float acc[8][8];
#pragma unroll
    for (int i = 0; i < 8; i++)
#pragma unroll
        for (int j = 0; j < 8; j++) acc[i][j] = 0.0f;

    float4 ar = avalid ? *(const float4*)(aptr) : make_float4(0.f,0.f,0.f,0.f);
    float4 br = *(const float4*)(bptr);

    const int KT = DIM / 8;
    for (int kt = 0; kt < KT; kt++) {
        As[lk+0][lr] = ar.x; As[lk+1][lr] = ar.y; As[lk+2][lr] = ar.z; As[lk+3][lr] = ar.w;
        Bs[lk+0][lr] = br.x; Bs[lk+1][lr] = br.y; Bs[lk+2][lr] = br.z; Bs[lk+3][lr] = br.w;
        __syncthreads();

        if (kt + 1 < KT) {
            int ko = (kt + 1) * 8;
            ar = avalid ? *(const float4*)(aptr + ko) : make_float4(0.f,0.f,0.f,0.f);
            br = *(const float4*)(bptr + ko);
        }

#pragma unroll
        for (int kk = 0; kk < 8; kk++) {
            float a[8], b[8];
#pragma unroll
            for (int i = 0; i < 8; i++) a[i] = As[kk][ty * 8 + i];
#pragma unroll
            for (int j = 0; j < 8; j++) b[j] = Bs[kk][tx * 8 + j];
#pragma unroll
            for (int i = 0; i < 8; i++)
#pragma unroll
                for (int j = 0; j < 8; j++) acc[i][j] += a[i] * b[j];
        }
        __syncthreads();
    }

#pragma unroll
    for (int i = 0; i < 8; i++) {
        int m = m0 + ty * 8 + i;
        if (m < n_e) {
            float* hrow = g_H + ((size_t)(base + m)) * HDIM + n0 + tx * 8;
            float4 v0, v1;
            float t0;
            t0 = acc[i][0]; v0.x = t0 > 0.f ? t0 * t0 : 0.f;
            t0 = acc[i][1]; v0.y = t0 > 0.f ? t0 * t0 : 0.f;
            t0 = acc[i][2]; v0.z = t0 > 0.f ? t0 * t0 : 0.f;
            t0 = acc[i][3]; v0.w = t0 > 0.f ? t0 * t0 : 0.f;
            t0 = acc[i][4]; v1.x = t0 > 0.f ? t0 * t0 : 0.f;
            t0 = acc[i][5]; v1.y = t0 > 0.f ? t0 * t0 : 0.f;
            t0 = acc[i][6]; v1.z = t0 > 0.f ? t0 * t0 : 0.f;
            t0 = acc[i][7]; v1.w = t0 > 0.f ? t0 * t0 : 0.f;
            *(float4*)(hrow)     = v0;
            *(float4*)(hrow + 4) = v1;
        }
    }
}

// --------------------------------------------------------------------------
// GEMM2: per expert, Y[m,n] = sum_k H[m,k] * fc2[e][n][k]; write wt*Y to slot.
__global__ __launch_bounds__(256) void gemm2_kernel(const float* __restrict__ fc2)
{
    int e    = blockIdx.z;
    int n_e  = g_counts[e];
    int m0   = blockIdx.x * 128;
    if (m0 >= n_e) return;
    int base = g_base[e];
    int n0   = blockIdx.y * 128;

    __shared__ float As[8][128];
    __shared__ float Bs[8][128];

    int tid = threadIdx.x;
    int lr  = tid >> 1;
    int lk  = (tid & 1) * 4;

    int gm = m0 + lr;
    bool avalid = (gm < n_e);
    const float* aptr = g_H + ((size_t)(base + gm)) * HDIM + lk;
    const float* bptr = fc2 + (size_t)e * DIM * HDIM + (size_t)(n0 + lr) * HDIM + lk;

    int tx = tid & 15, ty = tid >> 4;

    float acc[8][8];
#pragma unroll
    for (int i = 0; i < 8; i++)
#pragma unroll
        for (int j = 0; j < 8; j++) acc[i][j] = 0.0f;

    float4 ar = avalid ? *(const float4*)(aptr) : make_float4(0.f,0.f,0.f,0.f);
    float4 br = *(const float4*)(bptr);

    const int KT = HDIM / 8;
    for (int kt = 0; kt < KT; kt++) {
        As[lk+0][lr] = ar.x; As[lk+1][lr] = ar.y; As[lk+2][lr] = ar.z; As[lk+3][lr] = ar.w;
        Bs[lk+0][lr] = br.x; Bs[lk+1][lr] = br.y; Bs[lk+2][lr] = br.z; Bs[lk+3][lr] = br.w;
        __syncthreads();

        if (kt + 1 < KT) {
            int ko = (kt + 1) * 8;
            ar = avalid ? *(const float4*)(aptr + ko) : make_float4(0.f,0.f,0.f,0.f);
            br = *(const float4*)(bptr + ko);
        }

#pragma unroll
        for (int kk = 0; kk < 8; kk++) {
            float a[8], b[8];
#pragma unroll
            for (int i = 0; i < 8; i++) a[i] = As[kk][ty * 8 + i];
#pragma unroll
            for (int j = 0; j < 8; j++) b[j] = Bs[kk][tx * 8 + j];
#pragma unroll
            for (int i = 0; i < 8; i++)
#pragma unroll
                for (int j = 0; j < 8; j++) acc[i][j] += a[i] * b[j];
        }
        __syncthreads();
    }

#pragma unroll
    for (int i = 0; i < 8; i++) {
        int m = m0 + ty * 8 + i;
        if (m < n_e) {
            float w   = g_wt[e * CAP + m];
            int   gid = g_tok[e * CAP + m];
            float* srow = g_S + (size_t)gid * DIM + n0 + tx * 8;
            float4 v0, v1;
            v0.x = w * acc[i][0]; v0.y = w * acc[i][1];
            v0.z = w * acc[i][2]; v0.w = w * acc[i][3];
            v1.x = w * acc[i][4]; v1.y = w * acc[i][5];
            v1.z = w * acc[i][6]; v1.w = w * acc[i][7];
            *(float4*)(srow)     = v0;
            *(float4*)(srow + 4) = v1;
        }
    }
}

// --------------------------------------------------------------------------
__global__ __launch_bounds__(256) void combine_kernel(float* __restrict__ out)
{
    size_t i = (size_t)blockIdx.x * blockDim.x + threadIdx.x;  // float4 index
    const size_t d4 = DIM / 4;
    size_t t = i / d4;
    size_t c = i % d4;
    const float4* s = (const float4*)g_S;
    float4 p = s[(2 * t) * d4 + c];
    float4 q = s[(2 * t + 1) * d4 + c];
    float4 r;
    r.x = p.x + q.x; r.y = p.y + q.y; r.z = p.z + q.z; r.w = p.w + q.w;
    ((float4*)out)[i] = r;
}

// --------------------------------------------------------------------------
extern "C" void kernel_launch(void* const* d_in, const int* in_sizes, int n_in,
                              void* d_out, int out_size)
{
    const float* x   = (const float*)d_in[0];   // [4,2048,1024]
    const float* rw  = (const float*)d_in[1];   // [8,1024]
    const float* fc1 = (const float*)d_in[2];   // [8,2048,1024]
    const float* fc2 = (const float*)d_in[3];   // [8,1024,2048]
    float* out = (float*)d_out;

    zero_counts_kernel<<<1, 32>>>();
    router_kernel<<<N_TOK / 8, 256>>>(x, rw);
    scan_kernel<<<1, 32>>>();
    gemm1_kernel<<<dim3(CAP / 128, HDIM / 128, NEXP), 256>>>(x, fc1);
    gemm2_kernel<<<dim3(CAP / 128, DIM / 128, NEXP), 256>>>(fc2);
    combine_kernel<<<(N_TOK * DIM / 4) / 256, 256>>>(out);
}

// round 6
// speedup vs baseline: 2.0222x; 2.0222x over previous
#include <cuda_runtime.h>
#include <cuda_bf16.h>
#include <cstdint>

#define N_TOK 8192
#define DIM   1024
#define NEXP  8
#define HDIM  2048
#define CAP   8192
#define NSLOT (N_TOK * 2)

typedef __nv_bfloat16 bf16;

// ---------------- scratch: single 256MB pool, time-multiplexed -------------
// Phase 1 (gather/convert1/gemm1):  A  [0,64MB)   W1 [64,128MB)  H [128,256MB)
// Phase 2 (convert2/gemm2/combine): W2 [0,64MB)   S  [64,128MB)  H [128,256MB)
__device__ __align__(256) unsigned char g_pool[268435456];
#define P_AH  ((bf16*)(g_pool))
#define P_AL  ((bf16*)(g_pool + (32u << 20)))
#define P_W1H ((bf16*)(g_pool + (64u << 20)))
#define P_W1L ((bf16*)(g_pool + (96u << 20)))
#define P_HH  ((bf16*)(g_pool + (128u << 20)))
#define P_HL  ((bf16*)(g_pool + (192u << 20)))
#define P_W2H ((bf16*)(g_pool))
#define P_W2L ((bf16*)(g_pool + (32u << 20)))
#define P_S   ((float*)(g_pool + (64u << 20)))

__device__ int   g_counts[NEXP];
__device__ int   g_base[NEXP];
__device__ int   g_tok[NEXP * CAP];
__device__ float g_wt [NEXP * CAP];

// ---------------- PTX helpers (base sm_100-safe) ---------------------------
__device__ __forceinline__ uint32_t smem_to_u32(const void* p) {
    uint32_t a;
    asm("{ .reg .u64 t; cvta.to.shared.u64 t, %1; cvt.u32.u64 %0, t; }" : "=r"(a) : "l"(p));
    return a;
}
__device__ __forceinline__ void mma_bf16(float* c, const uint32_t* a, uint32_t b0, uint32_t b1) {
    asm volatile(
        "mma.sync.aligned.m16n8k16.row.col.f32.bf16.bf16.f32 "
        "{%0,%1,%2,%3},{%4,%5,%6,%7},{%8,%9},{%0,%1,%2,%3};"
        : "+f"(c[0]), "+f"(c[1]), "+f"(c[2]), "+f"(c[3])
        : "r"(a[0]), "r"(a[1]), "r"(a[2]), "r"(a[3]), "r"(b0), "r"(b1));
}
__device__ __forceinline__ void ldsm4(uint32_t* r, uint32_t addr) {
    asm volatile("ldmatrix.sync.aligned.m8n8.x4.shared.b16 {%0,%1,%2,%3},[%4];"
                 : "=r"(r[0]), "=r"(r[1]), "=r"(r[2]), "=r"(r[3]) : "r"(addr));
}
__device__ __forceinline__ void cpasync16(uint32_t dst, const void* src, int sz) {
    asm volatile("cp.async.cg.shared.global [%0],[%1],16,%2;"
                 :: "r"(dst), "l"(src), "r"(sz) : "memory");
}
#define CP_COMMIT() asm volatile("cp.async.commit_group;" ::: "memory")
#define CP_WAIT(N)  asm volatile("cp.async.wait_group %0;" :: "n"(N) : "memory")

// ---------------- split helpers -------------------------------------------
__device__ __forceinline__ void split4(float4 v, uint32_t& h01, uint32_t& h23,
                                       uint32_t& l01, uint32_t& l23) {
    __nv_bfloat162 h_01, h_23, l_01, l_23;
    bf16 h;
    h = __float2bfloat16_rn(v.x); h_01.x = h; l_01.x = __float2bfloat16_rn(v.x - __bfloat162float(h));
    h = __float2bfloat16_rn(v.y); h_01.y = h; l_01.y = __float2bfloat16_rn(v.y - __bfloat162float(h));
    h = __float2bfloat16_rn(v.z); h_23.x = h; l_23.x = __float2bfloat16_rn(v.z - __bfloat162float(h));
    h = __float2bfloat16_rn(v.w); h_23.y = h; l_23.y = __float2bfloat16_rn(v.w - __bfloat162float(h));
    h01 = *(uint32_t*)&h_01; h23 = *(uint32_t*)&h_23;
    l01 = *(uint32_t*)&l_01; l23 = *(uint32_t*)&l_23;
}

// ---------------- prep kernels --------------------------------------------
__global__ void zero_counts_kernel() { if (threadIdx.x < NEXP) g_counts[threadIdx.x] = 0; }

__global__ void scan_kernel() {
    if (threadIdx.x == 0) {
        int acc = 0;
#pragma unroll
        for (int e = 0; e < NEXP; e++) { g_base[e] = acc; acc += g_counts[e]; }
    }
}

__global__ __launch_bounds__(256) void router_kernel(
    const float* __restrict__ x, const float* __restrict__ rw)
{
    __shared__ float s_rw[NEXP * DIM];
    int tid = threadIdx.x;
    for (int i = tid; i < NEXP * DIM; i += 256) s_rw[i] = rw[i];
    __syncthreads();

    int warp = tid >> 5, lane = tid & 31;
    int t = blockIdx.x * 8 + warp;
    const float* xr = x + (size_t)t * DIM;

    float acc[NEXP];
#pragma unroll
    for (int e = 0; e < NEXP; e++) acc[e] = 0.0f;
    for (int j = lane; j < DIM; j += 32) {
        float xv = xr[j];
#pragma unroll
        for (int e = 0; e < NEXP; e++) acc[e] += xv * s_rw[e * DIM + j];
    }
#pragma unroll
    for (int e = 0; e < NEXP; e++)
#pragma unroll
        for (int off = 16; off > 0; off >>= 1)
            acc[e] += __shfl_xor_sync(0xFFFFFFFFu, acc[e], off);

    if (lane == 0) {
        int e0 = 0; float l0 = acc[0];
#pragma unroll
        for (int e = 1; e < NEXP; e++) if (acc[e] > l0) { l0 = acc[e]; e0 = e; }
        int e1 = -1; float l1 = -3.0e38f;
#pragma unroll
        for (int e = 0; e < NEXP; e++) if (e != e0 && acc[e] > l1) { l1 = acc[e]; e1 = e; }
        float w0 = 1.0f / (1.0f + expf(l1 - l0));
        float w1 = 1.0f - w0;
        int p0 = atomicAdd(&g_counts[e0], 1);
        g_tok[e0 * CAP + p0] = t * 2;     g_wt[e0 * CAP + p0] = w0;
        int p1 = atomicAdd(&g_counts[e1], 1);
        g_tok[e1 * CAP + p1] = t * 2 + 1; g_wt[e1 * CAP + p1] = w1;
    }
}

__global__ __launch_bounds__(256) void gather_x_kernel(const float* __restrict__ x)
{
    int e = blockIdx.y;
    int i = blockIdx.x * 8 + (threadIdx.x >> 5);
    if (i >= g_counts[e]) return;
    int lane = threadIdx.x & 31;
    int t = g_tok[e * CAP + i] >> 1;
    size_t dst = (size_t)(g_base[e] + i) * DIM;
    bf16* Ah = P_AH; bf16* Al = P_AL;
    const float4* src = (const float4*)(x + (size_t)t * DIM);
    for (int c = lane; c < DIM / 4; c += 32) {
        uint32_t h01, h23, l01, l23;
        split4(src[c], h01, h23, l01, l23);
        *(uint2*)(Ah + dst + c * 4) = make_uint2(h01, h23);
        *(uint2*)(Al + dst + c * 4) = make_uint2(l01, l23);
    }
}

template <int W>
__global__ __launch_bounds__(256) void convert_w_kernel(const float* __restrict__ src)
{
    bf16* dh = W ? P_W2H : P_W1H;
    bf16* dl = W ? P_W2L : P_W1L;
    size_t i = (size_t)blockIdx.x * 256 + threadIdx.x;     // float4 index
    float4 v = ((const float4*)src)[i];
    uint32_t h01, h23, l01, l23;
    split4(v, h01, h23, l01, l23);
    *(uint2*)(dh + i * 4) = make_uint2(h01, h23);
    *(uint2*)(dl + i * 4) = make_uint2(l01, l23);
}

// ---------------- mma.sync grouped GEMM ------------------------------------
// Block 128x128, 8 warps (2x4), warp tile 64x32, K-chunk 16, double-buffer
// cp.async, STATIC 48KB smem (no cudaFuncSetAttribute).
// 3-term split-bf16: D += Ah*Bh + Ah*Bl + Al*Bh (fp32 accum).
// Plane: 128 rows x 48B (16 halves + 8 pad) = 6144B. 4 planes x 2 bufs = 48KB.
#define RS      48
#define PLANE   6144
#define BUFSZ   (4 * PLANE)

template <int EPI>
__global__ __launch_bounds__(256, 1) void moe_gemm_mma()
{
    constexpr int KTOT = EPI ? HDIM : DIM;
    constexpr int NTOT = EPI ? DIM : HDIM;
    constexpr int NCH  = KTOT / 16;

    int e   = blockIdx.z;
    int n_e = g_counts[e];
    int m0  = blockIdx.x * 128;
    if (m0 >= n_e) return;
    int base = g_base[e];
    int n0   = blockIdx.y * 128;

    const bf16* __restrict__ Ah = EPI ? P_HH  : P_AH;
    const bf16* __restrict__ Al = EPI ? P_HL  : P_AL;
    const bf16* __restrict__ Bh = EPI ? P_W2H : P_W1H;
    const bf16* __restrict__ Bl = EPI ? P_W2L : P_W1L;

    __shared__ __align__(16) char smem[2 * BUFSZ];
    uint32_t sb = smem_to_u32(smem);
    int tid = threadIdx.x, wid = tid >> 5, lane = tid & 31;
    int wm = wid >> 2, wn = wid & 3;           // warp grid 2x4

    // ---- copy descriptors: 1 seg of 16B per plane per thread per chunk
    int row = tid >> 1, seg = tid & 1;         // 128 rows x 2 segs
    int gmr = m0 + row;
    int av  = (gmr < n_e) ? 16 : 0;
    size_t aoff = (size_t)(base + (av ? gmr : 0)) * KTOT;
    size_t boff = ((size_t)e * NTOT + n0 + row) * KTOT;
    uint32_t dsta = sb + row * RS + seg * 16;

    float acc[4][4][4];
#pragma unroll
    for (int i = 0; i < 4; i++)
#pragma unroll
        for (int j = 0; j < 4; j++)
#pragma unroll
            for (int k = 0; k < 4; k++) acc[i][j][k] = 0.0f;

    auto load_chunk = [&](int c) {
        uint32_t bo = (uint32_t)((c & 1) * BUFSZ);
        size_t k = (size_t)c * 16 + seg * 8;   // halves
        cpasync16(dsta + bo,             Ah + aoff + k, av);
        cpasync16(dsta + bo + PLANE,     Al + aoff + k, av);
        cpasync16(dsta + bo + 2 * PLANE, Bh + boff + k, 16);
        cpasync16(dsta + bo + 3 * PLANE, Bl + boff + k, 16);
        CP_COMMIT();
    };

    // ldmatrix lane addressing
    int lt = lane >> 3, lr = lane & 7;
    int a_row = (lt & 1) * 8 + lr, a_kt = (lt >> 1) * 8;   // A tiles: m8 x k8
    int b_n   = (lt >> 1) * 8 + lr, b_kt = (lt & 1) * 8;   // B tiles: n8 x k8

    load_chunk(0);
    for (int c = 0; c < NCH; c++) {
        if (c + 1 < NCH) { load_chunk(c + 1); CP_WAIT(1); }
        else             { CP_WAIT(0); }
        __syncthreads();

        uint32_t buf = sb + (uint32_t)((c & 1) * BUFSZ);
        uint32_t ah[4][4], al[4][4], bh[2][4], bl[2][4];
#pragma unroll
        for (int mt = 0; mt < 4; mt++) {
            uint32_t ad = buf + (wm * 64 + mt * 16 + a_row) * RS + a_kt * 2;
            ldsm4(ah[mt], ad);
            ldsm4(al[mt], ad + PLANE);
        }
#pragma unroll
        for (int ng = 0; ng < 2; ng++) {
            uint32_t bd = buf + 2 * PLANE + (wn * 32 + ng * 16 + b_n) * RS + b_kt * 2;
            ldsm4(bh[ng], bd);
            ldsm4(bl[ng], bd + PLANE);
        }
#pragma unroll
        for (int mt = 0; mt < 4; mt++)
#pragma unroll
            for (int nt = 0; nt < 4; nt++) {
                uint32_t bh0 = bh[nt >> 1][(nt & 1) * 2], bh1 = bh[nt >> 1][(nt & 1) * 2 + 1];
                uint32_t bl0 = bl[nt >> 1][(nt & 1) * 2], bl1 = bl[nt >> 1][(nt & 1) * 2 + 1];
                mma_bf16(acc[mt][nt], ah[mt], bh0, bh1);
                mma_bf16(acc[mt][nt], ah[mt], bl0, bl1);
                mma_bf16(acc[mt][nt], al[mt], bh0, bh1);
            }
        __syncthreads();
    }

    // ---- epilogue: c-frag lane l: rows g=l>>2 and g+8, col pair (l&3)*2
    bf16* Hh = P_HH; bf16* Hl = P_HL; float* S = P_S;
    int cg = lane >> 2, ct = (lane & 3) * 2;
#pragma unroll
    for (int mt = 0; mt < 4; mt++) {
        int r0 = m0 + wm * 64 + mt * 16 + cg;
        int r1 = r0 + 8;
#pragma unroll
        for (int nt = 0; nt < 4; nt++) {
            int col = n0 + wn * 32 + nt * 8 + ct;
            float* a4 = acc[mt][nt];
            if (EPI == 0) {
#pragma unroll
                for (int h = 0; h < 2; h++) {
                    int r = h ? r1 : r0;
                    if (r < n_e) {
                        float v0 = a4[h * 2], v1 = a4[h * 2 + 1];
                        float h0 = v0 > 0.f ? v0 * v0 : 0.f;
                        float h1 = v1 > 0.f ? v1 * v1 : 0.f;
                        __nv_bfloat162 hh, ll;
                        bf16 t0;
                        t0 = __float2bfloat16_rn(h0); hh.x = t0; ll.x = __float2bfloat16_rn(h0 - __bfloat162float(t0));
                        t0 = __float2bfloat16_rn(h1); hh.y = t0; ll.y = __float2bfloat16_rn(h1 - __bfloat162float(t0));
                        size_t o = (size_t)(base + r) * HDIM + col;
                        *(__nv_bfloat162*)(Hh + o) = hh;
                        *(__nv_bfloat162*)(Hl + o) = ll;
                    }
                }
            } else {
#pragma unroll
                for (int h = 0; h < 2; h++) {
                    int r = h ? r1 : r0;
                    if (r < n_e) {
                        float w   = g_wt[e * CAP + r];
                        int   gid = g_tok[e * CAP + r];
                        float2 v = make_float2(w * a4[h * 2], w * a4[h * 2 + 1]);
                        *(float2*)(S + (size_t)gid * DIM + col) = v;
                    }
                }
            }
        }
    }
}

// ---------------- combine --------------------------------------------------
__global__ __launch_bounds__(256) void combine_kernel(float* __restrict__ out)
{
    size_t i = (size_t)blockIdx.x * blockDim.x + threadIdx.x;  // float4 index
    const size_t d4 = DIM / 4;
    size_t t = i / d4, c = i % d4;
    const float4* s = (const float4*)P_S;
    float4 p = s[(2 * t) * d4 + c];
    float4 q = s[(2 * t + 1) * d4 + c];
    float4 r2;
    r2.x = p.x + q.x; r2.y = p.y + q.y; r2.z = p.z + q.z; r2.w = p.w + q.w;
    ((float4*)out)[i] = r2;
}

// ---------------- launch ----------------------------------------------------
extern "C" void kernel_launch(void* const* d_in, const int* in_sizes, int n_in,
                              void* d_out, int out_size)
{
    const float* x   = (const float*)d_in[0];   // [4,2048,1024]
    const float* rw  = (const float*)d_in[1];   // [8,1024]
    const float* fc1 = (const float*)d_in[2];   // [8,2048,1024]
    const float* fc2 = (const float*)d_in[3];   // [8,1024,2048]
    float* out = (float*)d_out;

    zero_counts_kernel<<<1, 32>>>();
    router_kernel<<<N_TOK / 8, 256>>>(x, rw);
    scan_kernel<<<1, 32>>>();
    gather_x_kernel<<<dim3(CAP / 8, NEXP), 256>>>(x);
    convert_w_kernel<0><<<(NEXP * HDIM * DIM / 4) / 256, 256>>>(fc1);
    moe_gemm_mma<0><<<dim3(CAP / 128, HDIM / 128, NEXP), 256>>>();
    convert_w_kernel<1><<<(NEXP * DIM * HDIM / 4) / 256, 256>>>(fc2);   // W2 overwrites A
    moe_gemm_mma<1><<<dim3(CAP / 128, DIM / 128, NEXP), 256>>>();       // S overwrites W1
    combine_kernel<<<(N_TOK * DIM / 4) / 256, 256>>>(out);
}

// round 7
// speedup vs baseline: 3.0868x; 1.5265x over previous
#include <cuda_runtime.h>
#include <cuda_fp16.h>
#include <cstdint>

#define N_TOK 8192
#define DIM   1024
#define NEXP  8
#define HDIM  2048
#define CAP   8192
#define NSLOT (N_TOK * 2)

// ---------------- scratch: single 192MB pool, time-multiplexed -------------
// Phase 1 (gather/convert1/gemm1):  Ah[0,32) Al[32,64) W1h[64,96) W1l[96,128) H[128,192)
// Phase 2 (convert2/gemm2/combine): W2h[0,32) W2l[32,64) S[64,128)           H[128,192)
__device__ __align__(256) unsigned char g_pool[201326592];
#define P_AH  ((half*)(g_pool))
#define P_AL  ((half*)(g_pool + (32u << 20)))
#define P_W1H ((half*)(g_pool + (64u << 20)))
#define P_W1L ((half*)(g_pool + (96u << 20)))
#define P_H   ((half*)(g_pool + (128u << 20)))
#define P_W2H ((half*)(g_pool))
#define P_W2L ((half*)(g_pool + (32u << 20)))
#define P_S   ((float*)(g_pool + (64u << 20)))

__device__ int   g_counts[NEXP];
__device__ int   g_base[NEXP];
__device__ int   g_tok[NEXP * CAP];
__device__ float g_wt [NEXP * CAP];

// ---------------- PTX helpers (base sm_100-safe) ---------------------------
__device__ __forceinline__ uint32_t smem_to_u32(const void* p) {
    uint32_t a;
    asm("{ .reg .u64 t; cvta.to.shared.u64 t, %1; cvt.u32.u64 %0, t; }" : "=r"(a) : "l"(p));
    return a;
}
__device__ __forceinline__ void mma_f16(float* c, const uint32_t* a, uint32_t b0, uint32_t b1) {
    asm volatile(
        "mma.sync.aligned.m16n8k16.row.col.f32.f16.f16.f32 "
        "{%0,%1,%2,%3},{%4,%5,%6,%7},{%8,%9},{%0,%1,%2,%3};"
        : "+f"(c[0]), "+f"(c[1]), "+f"(c[2]), "+f"(c[3])
        : "r"(a[0]), "r"(a[1]), "r"(a[2]), "r"(a[3]), "r"(b0), "r"(b1));
}
__device__ __forceinline__ void ldsm4(uint32_t* r, uint32_t addr) {
    asm volatile("ldmatrix.sync.aligned.m8n8.x4.shared.b16 {%0,%1,%2,%3},[%4];"
                 : "=r"(r[0]), "=r"(r[1]), "=r"(r[2]), "=r"(r[3]) : "r"(addr));
}
__device__ __forceinline__ void cpasync16(uint32_t dst, const void* src, int sz) {
    asm volatile("cp.async.cg.shared.global [%0],[%1],16,%2;"
                 :: "r"(dst), "l"(src), "r"(sz) : "memory");
}
#define CP_COMMIT() asm volatile("cp.async.commit_group;" ::: "memory")
#define CP_WAIT(N)  asm volatile("cp.async.wait_group %0;" :: "n"(N) : "memory")

// Swizzled plane: 128 rows x 32B; 16B-granular XOR keeps ldmatrix phases and
// cp.async store phases conflict-free.
__device__ __forceinline__ uint32_t swz(int row, int byte) {
    return (uint32_t)(row * 32 + (byte ^ ((row & 4) << 2)));
}

// ---------------- split helpers (fp16 hi/lo) -------------------------------
__device__ __forceinline__ void split4h(float4 v, uint32_t& h01, uint32_t& h23,
                                        uint32_t& l01, uint32_t& l23) {
    __half2 H01, H23, L01, L23;
    half h;
    h = __float2half_rn(v.x); H01.x = h; L01.x = __float2half_rn(v.x - __half2float(h));
    h = __float2half_rn(v.y); H01.y = h; L01.y = __float2half_rn(v.y - __half2float(h));
    h = __float2half_rn(v.z); H23.x = h; L23.x = __float2half_rn(v.z - __half2float(h));
    h = __float2half_rn(v.w); H23.y = h; L23.y = __float2half_rn(v.w - __half2float(h));
    h01 = *(uint32_t*)&H01; h23 = *(uint32_t*)&H23;
    l01 = *(uint32_t*)&L01; l23 = *(uint32_t*)&L23;
}

// ---------------- prep kernels --------------------------------------------
__global__ void zero_counts_kernel() { if (threadIdx.x < NEXP) g_counts[threadIdx.x] = 0; }

__global__ void scan_kernel() {
    if (threadIdx.x == 0) {
        int acc = 0;
#pragma unroll
        for (int e = 0; e < NEXP; e++) { g_base[e] = acc; acc += g_counts[e]; }
    }
}

__global__ __launch_bounds__(256) void router_kernel(
    const float* __restrict__ x, const float* __restrict__ rw)
{
    __shared__ float s_rw[NEXP * DIM];
    int tid = threadIdx.x;
    for (int i = tid; i < NEXP * DIM; i += 256) s_rw[i] = rw[i];
    __syncthreads();

    int warp = tid >> 5, lane = tid & 31;
    int t = blockIdx.x * 8 + warp;
    const float* xr = x + (size_t)t * DIM;

    float acc[NEXP];
#pragma unroll
    for (int e = 0; e < NEXP; e++) acc[e] = 0.0f;
    for (int j = lane; j < DIM; j += 32) {
        float xv = xr[j];
#pragma unroll
        for (int e = 0; e < NEXP; e++) acc[e] += xv * s_rw[e * DIM + j];
    }
#pragma unroll
    for (int e = 0; e < NEXP; e++)
#pragma unroll
        for (int off = 16; off > 0; off >>= 1)
            acc[e] += __shfl_xor_sync(0xFFFFFFFFu, acc[e], off);

    if (lane == 0) {
        int e0 = 0; float l0 = acc[0];
#pragma unroll
        for (int e = 1; e < NEXP; e++) if (acc[e] > l0) { l0 = acc[e]; e0 = e; }
        int e1 = -1; float l1 = -3.0e38f;
#pragma unroll
        for (int e = 0; e < NEXP; e++) if (e != e0 && acc[e] > l1) { l1 = acc[e]; e1 = e; }
        float w0 = 1.0f / (1.0f + expf(l1 - l0));
        float w1 = 1.0f - w0;
        int p0 = atomicAdd(&g_counts[e0], 1);
        g_tok[e0 * CAP + p0] = t * 2;     g_wt[e0 * CAP + p0] = w0;
        int p1 = atomicAdd(&g_counts[e1], 1);
        g_tok[e1 * CAP + p1] = t * 2 + 1; g_wt[e1 * CAP + p1] = w1;
    }
}

__global__ __launch_bounds__(256) void gather_x_kernel(const float* __restrict__ x)
{
    int e = blockIdx.y;
    int i = blockIdx.x * 8 + (threadIdx.x >> 5);
    if (i >= g_counts[e]) return;
    int lane = threadIdx.x & 31;
    int t = g_tok[e * CAP + i] >> 1;
    size_t dst = (size_t)(g_base[e] + i) * DIM;
    half* Ah = P_AH; half* Al = P_AL;
    const float4* src = (const float4*)(x + (size_t)t * DIM);
    for (int c = lane; c < DIM / 4; c += 32) {
        uint32_t h01, h23, l01, l23;
        split4h(src[c], h01, h23, l01, l23);
        *(uint2*)(Ah + dst + c * 4) = make_uint2(h01, h23);
        *(uint2*)(Al + dst + c * 4) = make_uint2(l01, l23);
    }
}

template <int W>
__global__ __launch_bounds__(256) void convert_w_kernel(const float* __restrict__ src)
{
    half* dh = W ? P_W2H : P_W1H;
    half* dl = W ? P_W2L : P_W1L;
    size_t i = (size_t)blockIdx.x * 256 + threadIdx.x;     // float4 index
    float4 v = ((const float4*)src)[i];
    uint32_t h01, h23, l01, l23;
    split4h(v, h01, h23, l01, l23);
    *(uint2*)(dh + i * 4) = make_uint2(h01, h23);
    *(uint2*)(dl + i * 4) = make_uint2(l01, l23);
}

// ---------------- mma.sync grouped GEMM ------------------------------------
// Block 128x128, 8 warps (2x4), warp tile 64x32, K-chunk 16, multi-stage
// cp.async, STATIC 48KB smem, swizzled 32B-row planes, ONE sync per chunk.
// GEMM1 (EPI=0): 3 terms Ah*Bh + Ah*Bl + Al*Bh (near-exact), 4 planes, 3 stages.
// GEMM2 (EPI=1): 2 terms A*Bh + A*Bl (A=fp16(H), err ~2^-12), 3 planes, 4 stages.
#define PLANE 4096

template <int EPI>
__global__ __launch_bounds__(256, 1) void moe_gemm_mma()
{
    constexpr int KTOT = EPI ? HDIM : DIM;
    constexpr int NTOT = EPI ? DIM : HDIM;
    constexpr int NCH  = KTOT / 16;
    constexpr int NPL  = EPI ? 3 : 4;
    constexpr int NS   = EPI ? 4 : 3;
    constexpr int BUF  = NPL * PLANE;

    int e   = blockIdx.z;
    int n_e = g_counts[e];
    int m0  = blockIdx.x * 128;
    if (m0 >= n_e) return;
    int base = g_base[e];
    int n0   = blockIdx.y * 128;

    const half* __restrict__ Ah = EPI ? P_H   : P_AH;
    const half* __restrict__ Al = EPI ? P_H   : P_AL;   // unused when EPI
    const half* __restrict__ Bh = EPI ? P_W2H : P_W1H;
    const half* __restrict__ Bl = EPI ? P_W2L : P_W1L;

    __shared__ __align__(16) char smem[NS * BUF];
    uint32_t sb = smem_to_u32(smem);
    int tid = threadIdx.x, wid = tid >> 5, lane = tid & 31;
    int wm = wid >> 2, wn = wid & 3;           // warp grid 2x4

    // ---- copy descriptors: per thread one 16B seg per plane per chunk
    int row = tid >> 1, seg = tid & 1;         // 128 rows x 2 segs (32B/row)
    int gmr = m0 + row;
    int av  = (gmr < n_e) ? 16 : 0;
    size_t aoff = (size_t)(base + (av ? gmr : 0)) * KTOT;
    size_t boff = ((size_t)e * NTOT + n0 + row) * KTOT;
    uint32_t dsta = sb + swz(row, seg * 16);

    float acc[4][4][4];
#pragma unroll
    for (int i = 0; i < 4; i++)
#pragma unroll
        for (int j = 0; j < 4; j++)
#pragma unroll
            for (int k = 0; k < 4; k++) acc[i][j][k] = 0.0f;

    auto load_chunk = [&](int c) {
        uint32_t bo = (uint32_t)((c % NS) * BUF);
        size_t k = (size_t)c * 16 + seg * 8;   // halves
        if (EPI == 0) {
            cpasync16(dsta + bo,             Ah + aoff + k, av);
            cpasync16(dsta + bo + PLANE,     Al + aoff + k, av);
            cpasync16(dsta + bo + 2 * PLANE, Bh + boff + k, 16);
            cpasync16(dsta + bo + 3 * PLANE, Bl + boff + k, 16);
        } else {
            cpasync16(dsta + bo,             Ah + aoff + k, av);
            cpasync16(dsta + bo + PLANE,     Bh + boff + k, 16);
            cpasync16(dsta + bo + 2 * PLANE, Bl + boff + k, 16);
        }
        CP_COMMIT();
    };

    // ldmatrix lane addressing
    int lt = lane >> 3, lr = lane & 7;
    int a_row = (lt & 1) * 8 + lr, a_kt = (lt >> 1) * 8;   // A tiles: m8 x k8
    int b_n   = (lt >> 1) * 8 + lr, b_kt = (lt & 1) * 8;   // B tiles: n8 x k8

#pragma unroll
    for (int s = 0; s < NS - 1; s++) load_chunk(s);

    for (int c = 0; c < NCH; c++) {
        int rem = NCH - 1 - c;                 // groups newer than chunk c
        if (EPI == 0) { if (rem >= 1) CP_WAIT(1); else CP_WAIT(0); }
        else { if (rem >= 2) CP_WAIT(2); else if (rem == 1) CP_WAIT(1); else CP_WAIT(0); }
        __syncthreads();
        if (c + NS - 1 < NCH) load_chunk(c + NS - 1);

        uint32_t buf = sb + (uint32_t)((c % NS) * BUF);
        uint32_t ah[4][4], al[4][4], bh[2][4], bl[2][4];
#pragma unroll
        for (int mt = 0; mt < 4; mt++) {
            int r = wm * 64 + mt * 16 + a_row;
            uint32_t ad = buf + swz(r, a_kt * 2);
            ldsm4(ah[mt], ad);
            if (EPI == 0) ldsm4(al[mt], ad + PLANE);
        }
        uint32_t bpl = buf + (EPI ? PLANE : 2 * PLANE);
#pragma unroll
        for (int ng = 0; ng < 2; ng++) {
            int r = wn * 32 + ng * 16 + b_n;
            uint32_t bd = bpl + swz(r, b_kt * 2);
            ldsm4(bh[ng], bd);
            ldsm4(bl[ng], bd + PLANE);
        }
#pragma unroll
        for (int mt = 0; mt < 4; mt++)
#pragma unroll
            for (int nt = 0; nt < 4; nt++) {
                uint32_t bh0 = bh[nt >> 1][(nt & 1) * 2], bh1 = bh[nt >> 1][(nt & 1) * 2 + 1];
                uint32_t bl0 = bl[nt >> 1][(nt & 1) * 2], bl1 = bl[nt >> 1][(nt & 1) * 2 + 1];
                mma_f16(acc[mt][nt], ah[mt], bh0, bh1);
                mma_f16(acc[mt][nt], ah[mt], bl0, bl1);
                if (EPI == 0) mma_f16(acc[mt][nt], al[mt], bh0, bh1);
            }
    }

    // ---- epilogue: c-frag lane l: rows g=l>>2 and g+8, col pair (l&3)*2
    half* H = P_H; float* S = P_S;
    int cg = lane >> 2, ct = (lane & 3) * 2;
#pragma unroll
    for (int mt = 0; mt < 4; mt++) {
        int r0 = m0 + wm * 64 + mt * 16 + cg;
        int r1 = r0 + 8;
#pragma unroll
        for (int nt = 0; nt < 4; nt++) {
            int col = n0 + wn * 32 + nt * 8 + ct;
            float* a4 = acc[mt][nt];
            if (EPI == 0) {
#pragma unroll
                for (int h = 0; h < 2; h++) {
                    int r = h ? r1 : r0;
                    if (r < n_e) {
                        float v0 = a4[h * 2], v1 = a4[h * 2 + 1];
                        float h0 = v0 > 0.f ? v0 * v0 : 0.f;
                        float h1 = v1 > 0.f ? v1 * v1 : 0.f;
                        __half2 hv;
                        hv.x = __float2half_rn(h0);
                        hv.y = __float2half_rn(h1);
                        *(__half2*)(H + (size_t)(base + r) * HDIM + col) = hv;
                    }
                }
            } else {
#pragma unroll
                for (int h = 0; h < 2; h++) {
                    int r = h ? r1 : r0;
                    if (r < n_e) {
                        float w   = g_wt[e * CAP + r];
                        int   gid = g_tok[e * CAP + r];
                        float2 v = make_float2(w * a4[h * 2], w * a4[h * 2 + 1]);
                        *(float2*)(S + (size_t)gid * DIM + col) = v;
                    }
                }
            }
        }
    }
}

// ---------------- combine --------------------------------------------------
__global__ __launch_bounds__(256) void combine_kernel(float* __restrict__ out)
{
    size_t i = (size_t)blockIdx.x * blockDim.x + threadIdx.x;  // float4 index
    const size_t d4 = DIM / 4;
    size_t t = i / d4, c = i % d4;
    const float4* s = (const float4*)P_S;
    float4 p = s[(2 * t) * d4 + c];
    float4 q = s[(2 * t + 1) * d4 + c];
    float4 r2;
    r2.x = p.x + q.x; r2.y = p.y + q.y; r2.z = p.z + q.z; r2.w = p.w + q.w;
    ((float4*)out)[i] = r2;
}

// ---------------- launch ----------------------------------------------------
extern "C" void kernel_launch(void* const* d_in, const int* in_sizes, int n_in,
                              void* d_out, int out_size)
{
    const float* x   = (const float*)d_in[0];   // [4,2048,1024]
    const float* rw  = (const float*)d_in[1];   // [8,1024]
    const float* fc1 = (const float*)d_in[2];   // [8,2048,1024]
    const float* fc2 = (const float*)d_in[3];   // [8,1024,2048]
    float* out = (float*)d_out;

    zero_counts_kernel<<<1, 32>>>();
    router_kernel<<<N_TOK / 8, 256>>>(x, rw);
    scan_kernel<<<1, 32>>>();
    gather_x_kernel<<<dim3(CAP / 8, NEXP), 256>>>(x);
    convert_w_kernel<0><<<(NEXP * HDIM * DIM / 4) / 256, 256>>>(fc1);
    moe_gemm_mma<0><<<dim3(CAP / 128, HDIM / 128, NEXP), 256>>>();
    convert_w_kernel<1><<<(NEXP * DIM * HDIM / 4) / 256, 256>>>(fc2);   // W2 overwrites A
    moe_gemm_mma<1><<<dim3(CAP / 128, DIM / 128, NEXP), 256>>>();       // S overwrites W1
    combine_kernel<<<(N_TOK * DIM / 4) / 256, 256>>>(out);
}

// round 8
// speedup vs baseline: 4.8307x; 1.5650x over previous
#include <cuda_runtime.h>
#include <cuda_fp16.h>
#include <cstdint>

#define N_TOK 8192
#define DIM   1024
#define NEXP  8
#define HDIM  2048
#define CAP   8192
#define NSLOT (N_TOK * 2)

// ---------------- scratch: single 224MB pool, time-multiplexed -------------
// Phase 1 (gather/convert1/gemm1):  Ah[0,32) W1h[32,64) W1l[64,96) H[96,160)
// Phase 2 (convert2/gemm2/combine): W2h[0,32) W2l[32,64)           H[96,160) S[160,224)
__device__ __align__(256) unsigned char g_pool[234881024];
#define P_AH  ((half*)(g_pool))
#define P_W1H ((half*)(g_pool + (32u << 20)))
#define P_W1L ((half*)(g_pool + (64u << 20)))
#define P_H   ((half*)(g_pool + (96u << 20)))
#define P_W2H ((half*)(g_pool))
#define P_W2L ((half*)(g_pool + (32u << 20)))
#define P_S   ((float*)(g_pool + (160u << 20)))

__device__ int   g_counts[NEXP];
__device__ int   g_base[NEXP];
__device__ int   g_tok[NEXP * CAP];
__device__ float g_wt [NEXP * CAP];

// ---------------- PTX helpers (base sm_100-safe) ---------------------------
__device__ __forceinline__ uint32_t smem_to_u32(const void* p) {
    uint32_t a;
    asm("{ .reg .u64 t; cvta.to.shared.u64 t, %1; cvt.u32.u64 %0, t; }" : "=r"(a) : "l"(p));
    return a;
}
__device__ __forceinline__ void mma_f16(float* c, const uint32_t* a, uint32_t b0, uint32_t b1) {
    asm volatile(
        "mma.sync.aligned.m16n8k16.row.col.f32.f16.f16.f32 "
        "{%0,%1,%2,%3},{%4,%5,%6,%7},{%8,%9},{%0,%1,%2,%3};"
        : "+f"(c[0]), "+f"(c[1]), "+f"(c[2]), "+f"(c[3])
        : "r"(a[0]), "r"(a[1]), "r"(a[2]), "r"(a[3]), "r"(b0), "r"(b1));
}
__device__ __forceinline__ void ldsm4(uint32_t* r, uint32_t addr) {
    asm volatile("ldmatrix.sync.aligned.m8n8.x4.shared.b16 {%0,%1,%2,%3},[%4];"
                 : "=r"(r[0]), "=r"(r[1]), "=r"(r[2]), "=r"(r[3]) : "r"(addr));
}
__device__ __forceinline__ void cpasync16(uint32_t dst, const void* src, int sz) {
    asm volatile("cp.async.cg.shared.global [%0],[%1],16,%2;"
                 :: "r"(dst), "l"(src), "r"(sz) : "memory");
}
#define CP_COMMIT() asm volatile("cp.async.commit_group;" ::: "memory")
#define CP_WAIT(N)  asm volatile("cp.async.wait_group %0;" :: "n"(N) : "memory")

// Swizzled plane: 128 rows x 32B; 16B-granular XOR keeps ldmatrix phases and
// cp.async store phases conflict-free.
__device__ __forceinline__ uint32_t swz(int row, int byte) {
    return (uint32_t)(row * 32 + (byte ^ ((row & 4) << 2)));
}

// ---------------- split helpers (fp16 hi/lo) -------------------------------
__device__ __forceinline__ void split4h(float4 v, uint32_t& h01, uint32_t& h23,
                                        uint32_t& l01, uint32_t& l23) {
    __half2 H01, H23, L01, L23;
    half h;
    h = __float2half_rn(v.x); H01.x = h; L01.x = __float2half_rn(v.x - __half2float(h));
    h = __float2half_rn(v.y); H01.y = h; L01.y = __float2half_rn(v.y - __half2float(h));
    h = __float2half_rn(v.z); H23.x = h; L23.x = __float2half_rn(v.z - __half2float(h));
    h = __float2half_rn(v.w); H23.y = h; L23.y = __float2half_rn(v.w - __half2float(h));
    h01 = *(uint32_t*)&H01; h23 = *(uint32_t*)&H23;
    l01 = *(uint32_t*)&L01; l23 = *(uint32_t*)&L23;
}
__device__ __forceinline__ void cvt4h(float4 v, uint32_t& h01, uint32_t& h23) {
    __half2 H01, H23;
    H01.x = __float2half_rn(v.x); H01.y = __float2half_rn(v.y);
    H23.x = __float2half_rn(v.z); H23.y = __float2half_rn(v.w);
    h01 = *(uint32_t*)&H01; h23 = *(uint32_t*)&H23;
}

// ---------------- prep kernels --------------------------------------------
__global__ void zero_counts_kernel() { if (threadIdx.x < NEXP) g_counts[threadIdx.x] = 0; }

__global__ void scan_kernel() {
    if (threadIdx.x == 0) {
        int acc = 0;
#pragma unroll
        for (int e = 0; e < NEXP; e++) { g_base[e] = acc; acc += g_counts[e]; }
    }
}

__global__ __launch_bounds__(256) void router_kernel(
    const float* __restrict__ x, const float* __restrict__ rw)
{
    __shared__ float s_rw[NEXP * DIM];
    int tid = threadIdx.x;
    for (int i = tid; i < NEXP * DIM; i += 256) s_rw[i] = rw[i];
    __syncthreads();

    int warp = tid >> 5, lane = tid & 31;
    int t = blockIdx.x * 8 + warp;
    const float* xr = x + (size_t)t * DIM;

    float acc[NEXP];
#pragma unroll
    for (int e = 0; e < NEXP; e++) acc[e] = 0.0f;
    for (int j = lane; j < DIM; j += 32) {
        float xv = xr[j];
#pragma unroll
        for (int e = 0; e < NEXP; e++) acc[e] += xv * s_rw[e * DIM + j];
    }
#pragma unroll
    for (int e = 0; e < NEXP; e++)
#pragma unroll
        for (int off = 16; off > 0; off >>= 1)
            acc[e] += __shfl_xor_sync(0xFFFFFFFFu, acc[e], off);

    if (lane == 0) {
        int e0 = 0; float l0 = acc[0];
#pragma unroll
        for (int e = 1; e < NEXP; e++) if (acc[e] > l0) { l0 = acc[e]; e0 = e; }
        int e1 = -1; float l1 = -3.0e38f;
#pragma unroll
        for (int e = 0; e < NEXP; e++) if (e != e0 && acc[e] > l1) { l1 = acc[e]; e1 = e; }
        float w0 = 1.0f / (1.0f + expf(l1 - l0));
        float w1 = 1.0f - w0;
        int p0 = atomicAdd(&g_counts[e0], 1);
        g_tok[e0 * CAP + p0] = t * 2;     g_wt[e0 * CAP + p0] = w0;
        int p1 = atomicAdd(&g_counts[e1], 1);
        g_tok[e1 * CAP + p1] = t * 2 + 1; g_wt[e1 * CAP + p1] = w1;
    }
}

__global__ __launch_bounds__(256) void gather_x_kernel(const float* __restrict__ x)
{
    int e = blockIdx.y;
    int i = blockIdx.x * 8 + (threadIdx.x >> 5);
    if (i >= g_counts[e]) return;
    int lane = threadIdx.x & 31;
    int t = g_tok[e * CAP + i] >> 1;
    size_t dst = (size_t)(g_base[e] + i) * DIM;
    half* Ah = P_AH;
    const float4* src = (const float4*)(x + (size_t)t * DIM);
    for (int c = lane; c < DIM / 4; c += 32) {
        uint32_t h01, h23;
        cvt4h(src[c], h01, h23);
        *(uint2*)(Ah + dst + c * 4) = make_uint2(h01, h23);
    }
}

template <int W>
__global__ __launch_bounds__(256) void convert_w_kernel(const float* __restrict__ src)
{
    half* dh = W ? P_W2H : P_W1H;
    half* dl = W ? P_W2L : P_W1L;
    size_t i = (size_t)blockIdx.x * 256 + threadIdx.x;     // float4 index
    float4 v = ((const float4*)src)[i];
    uint32_t h01, h23, l01, l23;
    split4h(v, h01, h23, l01, l23);
    *(uint2*)(dh + i * 4) = make_uint2(h01, h23);
    *(uint2*)(dl + i * 4) = make_uint2(l01, l23);
}

// ---------------- mma.sync grouped GEMM ------------------------------------
// Block 128x128, 8 warps (2x4), warp tile 64x32, K-chunk 16, 4-stage cp.async,
// STATIC 48KB smem, swizzled 32B-row planes, ONE sync per chunk.
// Both GEMMs 2-term: A*Bh + A*Bl (B split exact; A-side fp16 error only).
// GEMM1 (EPI=0): A=fp16(x), B=fc1 -> relu^2 -> fp16 H.
// GEMM2 (EPI=1): A=H, B=fc2 -> * route weight -> fp32 S.
#define PLANE 4096
#define NPL   3
#define NS    4
#define BUF   (NPL * PLANE)

template <int EPI>
__global__ __launch_bounds__(256, 1) void moe_gemm_mma()
{
    constexpr int KTOT = EPI ? HDIM : DIM;
    constexpr int NTOT = EPI ? DIM : HDIM;
    constexpr int NCH  = KTOT / 16;

    int e   = blockIdx.z;
    int n_e = g_counts[e];
    int m0  = blockIdx.x * 128;
    if (m0 >= n_e) return;
    int base = g_base[e];
    int n0   = blockIdx.y * 128;

    const half* __restrict__ A  = EPI ? P_H   : P_AH;
    const half* __restrict__ Bh = EPI ? P_W2H : P_W1H;
    const half* __restrict__ Bl = EPI ? P_W2L : P_W1L;

    __shared__ __align__(16) char smem[NS * BUF];
    uint32_t sb = smem_to_u32(smem);
    int tid = threadIdx.x, wid = tid >> 5, lane = tid & 31;
    int wm = wid >> 2, wn = wid & 3;           // warp grid 2x4

    // ---- copy descriptors: per thread one 16B seg per plane per chunk
    int row = tid >> 1, seg = tid & 1;         // 128 rows x 2 segs (32B/row)
    int gmr = m0 + row;
    int av  = (gmr < n_e) ? 16 : 0;
    size_t aoff = (size_t)(base + (av ? gmr : 0)) * KTOT;
    size_t boff = ((size_t)e * NTOT + n0 + row) * KTOT;
    uint32_t dsta = sb + swz(row, seg * 16);

    float acc[4][4][4];
#pragma unroll
    for (int i = 0; i < 4; i++)
#pragma unroll
        for (int j = 0; j < 4; j++)
#pragma unroll
            for (int k = 0; k < 4; k++) acc[i][j][k] = 0.0f;

    auto load_chunk = [&](int c) {
        uint32_t bo = (uint32_t)((c % NS) * BUF);
        size_t k = (size_t)c * 16 + seg * 8;   // halves
        cpasync16(dsta + bo,             A  + aoff + k, av);
        cpasync16(dsta + bo + PLANE,     Bh + boff + k, 16);
        cpasync16(dsta + bo + 2 * PLANE, Bl + boff + k, 16);
        CP_COMMIT();
    };

    // ldmatrix lane addressing
    int lt = lane >> 3, lr = lane & 7;
    int a_row = (lt & 1) * 8 + lr, a_kt = (lt >> 1) * 8;   // A tiles: m8 x k8
    int b_n   = (lt >> 1) * 8 + lr, b_kt = (lt & 1) * 8;   // B tiles: n8 x k8

#pragma unroll
    for (int s = 0; s < NS - 1; s++) load_chunk(s);

    for (int c = 0; c < NCH; c++) {
        int rem = NCH - 1 - c;                 // chunks newer than c still coming
        if (rem >= 2) CP_WAIT(2); else if (rem == 1) CP_WAIT(1); else CP_WAIT(0);
        __syncthreads();
        if (c + NS - 1 < NCH) load_chunk(c + NS - 1);

        uint32_t buf = sb + (uint32_t)((c % NS) * BUF);
        uint32_t ah[4][4], bh[2][4], bl[2][4];
#pragma unroll
        for (int mt = 0; mt < 4; mt++) {
            int r = wm * 64 + mt * 16 + a_row;
            ldsm4(ah[mt], buf + swz(r, a_kt * 2));
        }
#pragma unroll
        for (int ng = 0; ng < 2; ng++) {
            int r = wn * 32 + ng * 16 + b_n;
            uint32_t bd = buf + PLANE + swz(r, b_kt * 2);
            ldsm4(bh[ng], bd);
            ldsm4(bl[ng], bd + PLANE);
        }
#pragma unroll
        for (int mt = 0; mt < 4; mt++)
#pragma unroll
            for (int nt = 0; nt < 4; nt++) {
                uint32_t bh0 = bh[nt >> 1][(nt & 1) * 2], bh1 = bh[nt >> 1][(nt & 1) * 2 + 1];
                uint32_t bl0 = bl[nt >> 1][(nt & 1) * 2], bl1 = bl[nt >> 1][(nt & 1) * 2 + 1];
                mma_f16(acc[mt][nt], ah[mt], bh0, bh1);
                mma_f16(acc[mt][nt], ah[mt], bl0, bl1);
            }
    }

    // ---- epilogue: c-frag lane l: rows g=l>>2 and g+8, col pair (l&3)*2
    half* H = P_H; float* S = P_S;
    int cg = lane >> 2, ct = (lane & 3) * 2;
#pragma unroll
    for (int mt = 0; mt < 4; mt++) {
        int r0 = m0 + wm * 64 + mt * 16 + cg;
        int r1 = r0 + 8;
#pragma unroll
        for (int nt = 0; nt < 4; nt++) {
            int col = n0 + wn * 32 + nt * 8 + ct;
            float* a4 = acc[mt][nt];
            if (EPI == 0) {
#pragma unroll
                for (int h = 0; h < 2; h++) {
                    int r = h ? r1 : r0;
                    if (r < n_e) {
                        float v0 = a4[h * 2], v1 = a4[h * 2 + 1];
                        float h0 = v0 > 0.f ? v0 * v0 : 0.f;
                        float h1 = v1 > 0.f ? v1 * v1 : 0.f;
                        __half2 hv;
                        hv.x = __float2half_rn(h0);
                        hv.y = __float2half_rn(h1);
                        *(__half2*)(H + (size_t)(base + r) * HDIM + col) = hv;
                    }
                }
            } else {
#pragma unroll
                for (int h = 0; h < 2; h++) {
                    int r = h ? r1 : r0;
                    if (r < n_e) {
                        float w   = g_wt[e * CAP + r];
                        int   gid = g_tok[e * CAP + r];
                        float2 v = make_float2(w * a4[h * 2], w * a4[h * 2 + 1]);
                        *(float2*)(S + (size_t)gid * DIM + col) = v;
                    }
                }
            }
        }
    }
}

// ---------------- combine --------------------------------------------------
__global__ __launch_bounds__(256) void combine_kernel(float* __restrict__ out)
{
    size_t i = (size_t)blockIdx.x * blockDim.x + threadIdx.x;  // float4 index
    const size_t d4 = DIM / 4;
    size_t t = i / d4, c = i % d4;
    const float4* s = (const float4*)P_S;
    float4 p = s[(2 * t) * d4 + c];
    float4 q = s[(2 * t + 1) * d4 + c];
    float4 r2;
    r2.x = p.x + q.x; r2.y = p.y + q.y; r2.z = p.z + q.z; r2.w = p.w + q.w;
    ((float4*)out)[i] = r2;
}

// ---------------- launch ----------------------------------------------------
extern "C" void kernel_launch(void* const* d_in, const int* in_sizes, int n_in,
                              void* d_out, int out_size)
{
    const float* x   = (const float*)d_in[0];   // [4,2048,1024]
    const float* rw  = (const float*)d_in[1];   // [8,1024]
    const float* fc1 = (const float*)d_in[2];   // [8,2048,1024]
    const float* fc2 = (const float*)d_in[3];   // [8,1024,2048]
    float* out = (float*)d_out;

    zero_counts_kernel<<<1, 32>>>();
    router_kernel<<<N_TOK / 8, 256>>>(x, rw);
    scan_kernel<<<1, 32>>>();
    gather_x_kernel<<<dim3(CAP / 8, NEXP), 256>>>(x);
    convert_w_kernel<0><<<(NEXP * HDIM * DIM / 4) / 256, 256>>>(fc1);
    moe_gemm_mma<0><<<dim3(CAP / 128, HDIM / 128, NEXP), 256>>>();
    convert_w_kernel<1><<<(NEXP * DIM * HDIM / 4) / 256, 256>>>(fc2);   // W2 overwrites A/W1h
    moe_gemm_mma<1><<<dim3(CAP / 128, DIM / 128, NEXP), 256>>>();
    combine_kernel<<<(N_TOK * DIM / 4) / 256, 256>>>(out);
}

// round 11
// speedup vs baseline: 5.2882x; 1.0947x over previous
#include <cuda_runtime.h>
#include <cuda_fp16.h>
#include <cstdint>

#define N_TOK 8192
#define DIM   1024
#define NEXP  8
#define HDIM  2048
#define CAP   8192
#define NSLOT (N_TOK * 2)

// ---------------- scratch: single 192MB pool, time-multiplexed -------------
// Phase 1 (gather/convert1/gemm1):  A[0,32) W1[32,64) H[64,128)
// Phase 2 (convert2/gemm2/combine): W2[32,64) H[64,128) S[128,192)
__device__ __align__(256) unsigned char g_pool[201326592];
#define P_A   ((half*)(g_pool))
#define P_W1  ((half*)(g_pool + (32u << 20)))
#define P_H   ((half*)(g_pool + (64u << 20)))
#define P_W2  ((half*)(g_pool + (32u << 20)))
#define P_S   ((float*)(g_pool + (128u << 20)))

__device__ int   g_counts[NEXP];
__device__ int   g_base[NEXP];
__device__ int   g_tok[NEXP * CAP];
__device__ float g_wt [NEXP * CAP];

// ---------------- PTX helpers (base sm_100-safe) ---------------------------
__device__ __forceinline__ uint32_t smem_to_u32(const void* p) {
    uint32_t a;
    asm("{ .reg .u64 t; cvta.to.shared.u64 t, %1; cvt.u32.u64 %0, t; }" : "=r"(a) : "l"(p));
    return a;
}
__device__ __forceinline__ void mma_f16(float* c, const uint32_t* a, uint32_t b0, uint32_t b1) {
    asm volatile(
        "mma.sync.aligned.m16n8k16.row.col.f32.f16.f16.f32 "
        "{%0,%1,%2,%3},{%4,%5,%6,%7},{%8,%9},{%0,%1,%2,%3};"
        : "+f"(c[0]), "+f"(c[1]), "+f"(c[2]), "+f"(c[3])
        : "r"(a[0]), "r"(a[1]), "r"(a[2]), "r"(a[3]), "r"(b0), "r"(b1));
}
__device__ __forceinline__ void ldsm4(uint32_t* r, uint32_t addr) {
    asm volatile("ldmatrix.sync.aligned.m8n8.x4.shared.b16 {%0,%1,%2,%3},[%4];"
                 : "=r"(r[0]), "=r"(r[1]), "=r"(r[2]), "=r"(r[3]) : "r"(addr));
}
__device__ __forceinline__ void cpasync16(uint32_t dst, const void* src, int sz) {
    asm volatile("cp.async.cg.shared.global [%0],[%1],16,%2;"
                 :: "r"(dst), "l"(src), "r"(sz) : "memory");
}
#define CP_COMMIT() asm volatile("cp.async.commit_group;" ::: "memory")
#define CP_WAIT(N)  asm volatile("cp.async.wait_group %0;" :: "n"(N) : "memory")

// Swizzled plane: 128 rows x 64B (K-chunk 32 halves).
// addr = row*64 + (byte ^ ((row&6)<<3)) — conflict-free for ldmatrix
// phases (8 rows hit 8 distinct 16B-bank groups) and cp.async stores.
__device__ __forceinline__ uint32_t swz64(int row, int byte) {
    return (uint32_t)(row * 64 + (byte ^ ((row & 6) << 3)));
}

// ---------------- convert helpers ------------------------------------------
__device__ __forceinline__ void cvt4h(float4 v, uint32_t& h01, uint32_t& h23) {
    __half2 H01, H23;
    H01.x = __float2half_rn(v.x); H01.y = __float2half_rn(v.y);
    H23.x = __float2half_rn(v.z); H23.y = __float2half_rn(v.w);
    h01 = *(uint32_t*)&H01; h23 = *(uint32_t*)&H23;
}

// ---------------- prep kernels --------------------------------------------
__global__ void zero_counts_kernel() { if (threadIdx.x < NEXP) g_counts[threadIdx.x] = 0; }

__global__ void scan_kernel() {
    if (threadIdx.x == 0) {
        int acc = 0;
#pragma unroll
        for (int e = 0; e < NEXP; e++) { g_base[e] = acc; acc += g_counts[e]; }
    }
}

__global__ __launch_bounds__(256) void router_kernel(
    const float* __restrict__ x, const float* __restrict__ rw)
{
    __shared__ float s_rw[NEXP * DIM];
    int tid = threadIdx.x;
    for (int i = tid; i < NEXP * DIM; i += 256) s_rw[i] = rw[i];
    __syncthreads();

    int warp = tid >> 5, lane = tid & 31;
    int t = blockIdx.x * 8 + warp;
    const float* xr = x + (size_t)t * DIM;

    float acc[NEXP];
#pragma unroll
    for (int e = 0; e < NEXP; e++) acc[e] = 0.0f;
    for (int j = lane; j < DIM; j += 32) {
        float xv = xr[j];
#pragma unroll
        for (int e = 0; e < NEXP; e++) acc[e] += xv * s_rw[e * DIM + j];
    }
#pragma unroll
    for (int e = 0; e < NEXP; e++)
#pragma unroll
        for (int off = 16; off > 0; off >>= 1)
            acc[e] += __shfl_xor_sync(0xFFFFFFFFu, acc[e], off);

    if (lane == 0) {
        int e0 = 0; float l0 = acc[0];
#pragma unroll
        for (int e = 1; e < NEXP; e++) if (acc[e] > l0) { l0 = acc[e]; e0 = e; }
        int e1 = -1; float l1 = -3.0e38f;
#pragma unroll
        for (int e = 0; e < NEXP; e++) if (e != e0 && acc[e] > l1) { l1 = acc[e]; e1 = e; }
        float w0 = 1.0f / (1.0f + expf(l1 - l0));
        float w1 = 1.0f - w0;
        int p0 = atomicAdd(&g_counts[e0], 1);
        g_tok[e0 * CAP + p0] = t * 2;     g_wt[e0 * CAP + p0] = w0;
        int p1 = atomicAdd(&g_counts[e1], 1);
        g_tok[e1 * CAP + p1] = t * 2 + 1; g_wt[e1 * CAP + p1] = w1;
    }
}

__global__ __launch_bounds__(256) void gather_x_kernel(const float* __restrict__ x)
{
    int e = blockIdx.y;
    int i = blockIdx.x * 8 + (threadIdx.x >> 5);
    if (i >= g_counts[e]) return;
    int lane = threadIdx.x & 31;
    int t = g_tok[e * CAP + i] >> 1;
    size_t dst = (size_t)(g_base[e] + i) * DIM;
    half* A = P_A;
    const float4* src = (const float4*)(x + (size_t)t * DIM);
    for (int c = lane; c < DIM / 4; c += 32) {
        uint32_t h01, h23;
        cvt4h(src[c], h01, h23);
        *(uint2*)(A + dst + c * 4) = make_uint2(h01, h23);
    }
}

template <int W>
__global__ __launch_bounds__(256) void convert_w_kernel(const float* __restrict__ src)
{
    half* dh = W ? P_W2 : P_W1;
    size_t i = (size_t)blockIdx.x * 256 + threadIdx.x;     // float4 index
    float4 v = ((const float4*)src)[i];
    uint32_t h01, h23;
    cvt4h(v, h01, h23);
    *(uint2*)(dh + i * 4) = make_uint2(h01, h23);
}

// ---------------- mma.sync grouped GEMM ------------------------------------
// Block 128x128, 8 warps (2x4), warp tile 64x32, K-chunk 32, 3-stage cp.async,
// STATIC 48KB smem, swizzled 64B-row planes, ONE sync per chunk.
// Single-term fp16 MMA (A and B both fp16; fp32 accum).
// GEMM1 (EPI=0): A=fp16(x), B=fp16(fc1) -> relu^2 -> fp16 H.
// GEMM2 (EPI=1): A=H, B=fp16(fc2) -> * route weight -> fp32 S.
#define PLANE 8192
#define NPL   2
#define NS    3
#define BUF   (NPL * PLANE)

template <int EPI>
__global__ __launch_bounds__(256, 1) void moe_gemm_mma()
{
    constexpr int KTOT = EPI ? HDIM : DIM;
    constexpr int NTOT = EPI ? DIM : HDIM;
    constexpr int NCH  = KTOT / 32;

    int e   = blockIdx.z;
    int n_e = g_counts[e];
    int m0  = blockIdx.x * 128;
    if (m0 >= n_e) return;
    int base = g_base[e];
    int n0   = blockIdx.y * 128;

    const half* __restrict__ A = EPI ? P_H  : P_A;
    const half* __restrict__ B = EPI ? P_W2 : P_W1;

    __shared__ __align__(16) char smem[NS * BUF];
    uint32_t sb = smem_to_u32(smem);
    int tid = threadIdx.x, wid = tid >> 5, lane = tid & 31;
    int wm = wid >> 2, wn = wid & 3;           // warp grid 2x4

    // ---- copy descriptors: 512 16B-slots per plane; thread t does slots t, t+256
    int row0 = tid >> 2, seg0 = tid & 3;                 // slots 0..255
    int row1 = (tid + 256) >> 2, seg1 = tid & 3;         // slots 256..511
    int gm0 = m0 + row0, gm1 = m0 + row1;
    int av0 = (gm0 < n_e) ? 16 : 0, av1 = (gm1 < n_e) ? 16 : 0;
    size_t aoff0 = (size_t)(base + (av0 ? gm0 : 0)) * KTOT;
    size_t aoff1 = (size_t)(base + (av1 ? gm1 : 0)) * KTOT;
    size_t boff0 = ((size_t)e * NTOT + n0 + row0) * KTOT;
    size_t boff1 = ((size_t)e * NTOT + n0 + row1) * KTOT;
    uint32_t dst0 = sb + swz64(row0, seg0 * 16);
    uint32_t dst1 = sb + swz64(row1, seg1 * 16);

    float acc[4][4][4];
#pragma unroll
    for (int i = 0; i < 4; i++)
#pragma unroll
        for (int j = 0; j < 4; j++)
#pragma unroll
            for (int k = 0; k < 4; k++) acc[i][j][k] = 0.0f;

    auto load_chunk = [&](int c) {
        uint32_t bo = (uint32_t)((c % NS) * BUF);
        size_t k0 = (size_t)c * 32 + seg0 * 8;   // halves
        cpasync16(dst0 + bo,         A + aoff0 + k0, av0);
        cpasync16(dst1 + bo,         A + aoff1 + k0, av1);
        cpasync16(dst0 + bo + PLANE, B + boff0 + k0, 16);
        cpasync16(dst1 + bo + PLANE, B + boff1 + k0, 16);
        CP_COMMIT();
    };

    // ldmatrix lane addressing
    int lt = lane >> 3, lr = lane & 7;
    int a_row = (lt & 1) * 8 + lr, a_kt = (lt >> 1) * 8;   // A tiles: m8 x k8
    int b_n   = (lt >> 1) * 8 + lr, b_kt = (lt & 1) * 8;   // B tiles: n8 x k8

#pragma unroll
    for (int s = 0; s < NS - 1; s++) load_chunk(s);

    for (int c = 0; c < NCH; c++) {
        int rem = NCH - 1 - c;
        if (rem >= 1) CP_WAIT(1); else CP_WAIT(0);
        __syncthreads();
        if (c + NS - 1 < NCH) load_chunk(c + NS - 1);

        uint32_t buf = sb + (uint32_t)((c % NS) * BUF);
#pragma unroll
        for (int ks = 0; ks < 2; ks++) {
            uint32_t ah[4][4], bh[2][4];
#pragma unroll
            for (int mt = 0; mt < 4; mt++) {
                int r = wm * 64 + mt * 16 + a_row;
                ldsm4(ah[mt], buf + swz64(r, ks * 32 + a_kt * 2));
            }
#pragma unroll
            for (int ng = 0; ng < 2; ng++) {
                int r = wn * 32 + ng * 16 + b_n;
                ldsm4(bh[ng], buf + PLANE + swz64(r, ks * 32 + b_kt * 2));
            }
#pragma unroll
            for (int mt = 0; mt < 4; mt++)
#pragma unroll
                for (int nt = 0; nt < 4; nt++) {
                    uint32_t b0 = bh[nt >> 1][(nt & 1) * 2], b1 = bh[nt >> 1][(nt & 1) * 2 + 1];
                    mma_f16(acc[mt][nt], ah[mt], b0, b1);
                }
        }
    }

    // ---- epilogue: c-frag lane l: rows g=l>>2 and g+8, col pair (l&3)*2
    half* H = P_H; float* S = P_S;
    int cg = lane >> 2, ct = (lane & 3) * 2;
#pragma unroll
    for (int mt = 0; mt < 4; mt++) {
        int r0 = m0 + wm * 64 + mt * 16 + cg;
        int r1 = r0 + 8;
#pragma unroll
        for (int nt = 0; nt < 4; nt++) {
            int col = n0 + wn * 32 + nt * 8 + ct;
            float* a4 = acc[mt][nt];
            if (EPI == 0) {
#pragma unroll
                for (int h = 0; h < 2; h++) {
                    int r = h ? r1 : r0;
                    if (r < n_e) {
                        float v0 = a4[h * 2], v1 = a4[h * 2 + 1];
                        float h0 = v0 > 0.f ? v0 * v0 : 0.f;
                        float h1 = v1 > 0.f ? v1 * v1 : 0.f;
                        __half2 hv;
                        hv.x = __float2half_rn(h0);
                        hv.y = __float2half_rn(h1);
                        *(__half2*)(H + (size_t)(base + r) * HDIM + col) = hv;
                    }
                }
            } else {
#pragma unroll
                for (int h = 0; h < 2; h++) {
                    int r = h ? r1 : r0;
                    if (r < n_e) {
                        float w   = g_wt[e * CAP + r];
                        int   gid = g_tok[e * CAP + r];
                        float2 v = make_float2(w * a4[h * 2], w * a4[h * 2 + 1]);
                        *(float2*)(S + (size_t)gid * DIM + col) = v;
                    }
                }
            }
        }
    }
}

// ---------------- combine --------------------------------------------------
__global__ __launch_bounds__(256) void combine_kernel(float* __restrict__ out)
{
    size_t i = (size_t)blockIdx.x * blockDim.x + threadIdx.x;  // float4 index
    const size_t d4 = DIM / 4;
    size_t t = i / d4, c = i % d4;
    const float4* s = (const float4*)P_S;
    float4 p = s[(2 * t) * d4 + c];
    float4 q = s[(2 * t + 1) * d4 + c];
    float4 r2;
    r2.x = p.x + q.x; r2.y = p.y + q.y; r2.z = p.z + q.z; r2.w = p.w + q.w;
    ((float4*)out)[i] = r2;
}

// ---------------- launch ----------------------------------------------------
extern "C" void kernel_launch(void* const* d_in, const int* in_sizes, int n_in,
                              void* d_out, int out_size)
{
    const float* x   = (const float*)d_in[0];   // [4,2048,1024]
    const float* rw  = (const float*)d_in[1];   // [8,1024]
    const float* fc1 = (const float*)d_in[2];   // [8,2048,1024]
    const float* fc2 = (const float*)d_in[3];   // [8,1024,2048]
    float* out = (float*)d_out;

    zero_counts_kernel<<<1, 32>>>();
    router_kernel<<<N_TOK / 8, 256>>>(x, rw);
    scan_kernel<<<1, 32>>>();
    gather_x_kernel<<<dim3(CAP / 8, NEXP), 256>>>(x);
    convert_w_kernel<0><<<(NEXP * HDIM * DIM / 4) / 256, 256>>>(fc1);
    moe_gemm_mma<0><<<dim3(CAP / 128, HDIM / 128, NEXP), 256>>>();
    convert_w_kernel<1><<<(NEXP * DIM * HDIM / 4) / 256, 256>>>(fc2);   // W2 overwrites W1
    moe_gemm_mma<1><<<dim3(CAP / 128, DIM / 128, NEXP), 256>>>();
    combine_kernel<<<(N_TOK * DIM / 4) / 256, 256>>>(out);
}

// round 12
// speedup vs baseline: 7.2763x; 1.3760x over previous
#include <cuda_runtime.h>
#include <cuda_fp16.h>
#include <cstdint>

#define N_TOK 8192
#define DIM   1024
#define NEXP  8
#define HDIM  2048
#define CAP   8192
#define NSLOT (N_TOK * 2)

// ---------------- scratch: single 192MB pool, time-multiplexed -------------
// Phase 1 (gather/convert1/gemm1):  A[0,32) W1[32,64) H[64,128)
// Phase 2 (convert2/gemm2/combine): W2[32,64) H[64,128) S[128,192)
__device__ __align__(256) unsigned char g_pool[201326592];
#define P_A   ((half*)(g_pool))
#define P_W1  ((half*)(g_pool + (32u << 20)))
#define P_H   ((half*)(g_pool + (64u << 20)))
#define P_W2  ((half*)(g_pool + (32u << 20)))
#define P_S   ((float*)(g_pool + (128u << 20)))

__device__ int   g_counts[NEXP];
__device__ int   g_base[NEXP];
__device__ int   g_tok[NEXP * CAP];
__device__ float g_wt [NEXP * CAP];

// ---------------- PTX helpers (base sm_100-safe) ---------------------------
__device__ __forceinline__ uint32_t smem_to_u32(const void* p) {
    uint32_t a;
    asm("{ .reg .u64 t; cvta.to.shared.u64 t, %1; cvt.u32.u64 %0, t; }" : "=r"(a) : "l"(p));
    return a;
}
__device__ __forceinline__ void mma_f16(float* c, const uint32_t* a, uint32_t b0, uint32_t b1) {
    asm volatile(
        "mma.sync.aligned.m16n8k16.row.col.f32.f16.f16.f32 "
        "{%0,%1,%2,%3},{%4,%5,%6,%7},{%8,%9},{%0,%1,%2,%3};"
        : "+f"(c[0]), "+f"(c[1]), "+f"(c[2]), "+f"(c[3])
        : "r"(a[0]), "r"(a[1]), "r"(a[2]), "r"(a[3]), "r"(b0), "r"(b1));
}
__device__ __forceinline__ void ldsm4(uint32_t* r, uint32_t addr) {
    asm volatile("ldmatrix.sync.aligned.m8n8.x4.shared.b16 {%0,%1,%2,%3},[%4];"
                 : "=r"(r[0]), "=r"(r[1]), "=r"(r[2]), "=r"(r[3]) : "r"(addr));
}
__device__ __forceinline__ void cpasync16(uint32_t dst, const void* src, int sz) {
    asm volatile("cp.async.cg.shared.global [%0],[%1],16,%2;"
                 :: "r"(dst), "l"(src), "r"(sz) : "memory");
}
#define CP_COMMIT() asm volatile("cp.async.commit_group;" ::: "memory")
#define CP_WAIT(N)  asm volatile("cp.async.wait_group %0;" :: "n"(N) : "memory")

// Swizzled plane: 128 rows x 64B (K-chunk 32 halves).
// addr = row*64 + (byte ^ ((row&6)<<3)) — conflict-free for ldmatrix
// phases (8 rows hit 8 distinct 16B-bank groups) and cp.async stores.
__device__ __forceinline__ uint32_t swz64(int row, int byte) {
    return (uint32_t)(row * 64 + (byte ^ ((row & 6) << 3)));
}

// ---------------- convert helpers ------------------------------------------
__device__ __forceinline__ void cvt4h(float4 v, uint32_t& h01, uint32_t& h23) {
    __half2 H01, H23;
    H01.x = __float2half_rn(v.x); H01.y = __float2half_rn(v.y);
    H23.x = __float2half_rn(v.z); H23.y = __float2half_rn(v.w);
    h01 = *(uint32_t*)&H01; h23 = *(uint32_t*)&H23;
}

// ---------------- prep kernels --------------------------------------------
__global__ void zero_counts_kernel() { if (threadIdx.x < NEXP) g_counts[threadIdx.x] = 0; }

__global__ void scan_kernel() {
    if (threadIdx.x == 0) {
        int acc = 0;
#pragma unroll
        for (int e = 0; e < NEXP; e++) { g_base[e] = acc; acc += g_counts[e]; }
    }
}

__global__ __launch_bounds__(256) void router_kernel(
    const float* __restrict__ x, const float* __restrict__ rw)
{
    __shared__ float s_rw[NEXP * DIM];
    int tid = threadIdx.x;
    for (int i = tid; i < NEXP * DIM; i += 256) s_rw[i] = rw[i];
    __syncthreads();

    int warp = tid >> 5, lane = tid & 31;
    int t = blockIdx.x * 8 + warp;
    const float* xr = x + (size_t)t * DIM;

    float acc[NEXP];
#pragma unroll
    for (int e = 0; e < NEXP; e++) acc[e] = 0.0f;
    for (int j = lane; j < DIM; j += 32) {
        float xv = xr[j];
#pragma unroll
        for (int e = 0; e < NEXP; e++) acc[e] += xv * s_rw[e * DIM + j];
    }
#pragma unroll
    for (int e = 0; e < NEXP; e++)
#pragma unroll
        for (int off = 16; off > 0; off >>= 1)
            acc[e] += __shfl_xor_sync(0xFFFFFFFFu, acc[e], off);

    if (lane == 0) {
        int e0 = 0; float l0 = acc[0];
#pragma unroll
        for (int e = 1; e < NEXP; e++) if (acc[e] > l0) { l0 = acc[e]; e0 = e; }
        int e1 = -1; float l1 = -3.0e38f;
#pragma unroll
        for (int e = 0; e < NEXP; e++) if (e != e0 && acc[e] > l1) { l1 = acc[e]; e1 = e; }
        float w0 = 1.0f / (1.0f + expf(l1 - l0));
        float w1 = 1.0f - w0;
        int p0 = atomicAdd(&g_counts[e0], 1);
        g_tok[e0 * CAP + p0] = t * 2;     g_wt[e0 * CAP + p0] = w0;
        int p1 = atomicAdd(&g_counts[e1], 1);
        g_tok[e1 * CAP + p1] = t * 2 + 1; g_wt[e1 * CAP + p1] = w1;
    }
}

__global__ __launch_bounds__(256) void gather_x_kernel(const float* __restrict__ x)
{
    int e = blockIdx.y;
    int i = blockIdx.x * 8 + (threadIdx.x >> 5);
    if (i >= g_counts[e]) return;
    int lane = threadIdx.x & 31;
    int t = g_tok[e * CAP + i] >> 1;
    size_t dst = (size_t)(g_base[e] + i) * DIM;
    half* A = P_A;
    const float4* src = (const float4*)(x + (size_t)t * DIM);
    for (int c = lane; c < DIM / 4; c += 32) {
        uint32_t h01, h23;
        cvt4h(src[c], h01, h23);
        *(uint2*)(A + dst + c * 4) = make_uint2(h01, h23);
    }
}

template <int W>
__global__ __launch_bounds__(256) void convert_w_kernel(const float* __restrict__ src)
{
    half* dh = W ? P_W2 : P_W1;
    size_t i = (size_t)blockIdx.x * 256 + threadIdx.x;     // float4 index
    float4 v = ((const float4*)src)[i];
    uint32_t h01, h23;
    cvt4h(v, h01, h23);
    *(uint2*)(dh + i * 4) = make_uint2(h01, h23);
}

// ---------------- mma.sync grouped GEMM ------------------------------------
// Block 128x128, 8 warps (2x4), warp tile 64x32, K-chunk 32, 3-stage cp.async,
// STATIC 48KB smem, swizzled 64B-row planes, ONE sync per chunk, 2 CTAs/SM.
// Single-term fp16 MMA (A and B both fp16; fp32 accum).
// GEMM1 (EPI=0): A=fp16(x), B=fp16(fc1) -> relu^2 -> fp16 H.
// GEMM2 (EPI=1): A=H, B=fp16(fc2) -> * route weight -> fp32 S.
#define PLANE 8192
#define NPL   2
#define NS    3
#define BUF   (NPL * PLANE)

template <int EPI>
__global__ __launch_bounds__(256, 2) void moe_gemm_mma()
{
    constexpr int KTOT = EPI ? HDIM : DIM;
    constexpr int NTOT = EPI ? DIM : HDIM;
    constexpr int NCH  = KTOT / 32;

    int e   = blockIdx.z;
    int n_e = g_counts[e];
    int m0  = blockIdx.x * 128;
    if (m0 >= n_e) return;
    int base = g_base[e];
    int n0   = blockIdx.y * 128;

    const half* __restrict__ A = EPI ? P_H  : P_A;
    const half* __restrict__ B = EPI ? P_W2 : P_W1;

    __shared__ __align__(16) char smem[NS * BUF];
    uint32_t sb = smem_to_u32(smem);
    int tid = threadIdx.x, wid = tid >> 5, lane = tid & 31;
    int wm = wid >> 2, wn = wid & 3;           // warp grid 2x4

    // ---- copy descriptors: 512 16B-slots per plane; thread t does slots t, t+256
    int row0 = tid >> 2, seg0 = tid & 3;                 // slots 0..255
    int row1 = (tid + 256) >> 2, seg1 = tid & 3;         // slots 256..511
    int gm0 = m0 + row0, gm1 = m0 + row1;
    int av0 = (gm0 < n_e) ? 16 : 0, av1 = (gm1 < n_e) ? 16 : 0;
    size_t aoff0 = (size_t)(base + (av0 ? gm0 : 0)) * KTOT;
    size_t aoff1 = (size_t)(base + (av1 ? gm1 : 0)) * KTOT;
    size_t boff0 = ((size_t)e * NTOT + n0 + row0) * KTOT;
    size_t boff1 = ((size_t)e * NTOT + n0 + row1) * KTOT;
    uint32_t dst0 = sb + swz64(row0, seg0 * 16);
    uint32_t dst1 = sb + swz64(row1, seg1 * 16);

    float acc[4][4][4];
#pragma unroll
    for (int i = 0; i < 4; i++)
#pragma unroll
        for (int j = 0; j < 4; j++)
#pragma unroll
            for (int k = 0; k < 4; k++) acc[i][j][k] = 0.0f;

    auto load_chunk = [&](int c) {
        uint32_t bo = (uint32_t)((c % NS) * BUF);
        size_t k0 = (size_t)c * 32 + seg0 * 8;   // halves
        cpasync16(dst0 + bo,         A + aoff0 + k0, av0);
        cpasync16(dst1 + bo,         A + aoff1 + k0, av1);
        cpasync16(dst0 + bo + PLANE, B + boff0 + k0, 16);
        cpasync16(dst1 + bo + PLANE, B + boff1 + k0, 16);
        CP_COMMIT();
    };

    // ldmatrix lane addressing
    int lt = lane >> 3, lr = lane & 7;
    int a_row = (lt & 1) * 8 + lr, a_kt = (lt >> 1) * 8;   // A tiles: m8 x k8
    int b_n   = (lt >> 1) * 8 + lr, b_kt = (lt & 1) * 8;   // B tiles: n8 x k8

#pragma unroll
    for (int s = 0; s < NS - 1; s++) load_chunk(s);

    for (int c = 0; c < NCH; c++) {
        int rem = NCH - 1 - c;
        if (rem >= 1) CP_WAIT(1); else CP_WAIT(0);
        __syncthreads();
        if (c + NS - 1 < NCH) load_chunk(c + NS - 1);

        uint32_t buf = sb + (uint32_t)((c % NS) * BUF);
#pragma unroll
        for (int ks = 0; ks < 2; ks++) {
            uint32_t ah[4][4], bh[2][4];
#pragma unroll
            for (int mt = 0; mt < 4; mt++) {
                int r = wm * 64 + mt * 16 + a_row;
                ldsm4(ah[mt], buf + swz64(r, ks * 32 + a_kt * 2));
            }
#pragma unroll
            for (int ng = 0; ng < 2; ng++) {
                int r = wn * 32 + ng * 16 + b_n;
                ldsm4(bh[ng], buf + PLANE + swz64(r, ks * 32 + b_kt * 2));
            }
#pragma unroll
            for (int mt = 0; mt < 4; mt++)
#pragma unroll
                for (int nt = 0; nt < 4; nt++) {
                    uint32_t b0 = bh[nt >> 1][(nt & 1) * 2], b1 = bh[nt >> 1][(nt & 1) * 2 + 1];
                    mma_f16(acc[mt][nt], ah[mt], b0, b1);
                }
        }
    }

    // ---- epilogue: c-frag lane l: rows g=l>>2 and g+8, col pair (l&3)*2
    half* H = P_H; float* S = P_S;
    int cg = lane >> 2, ct = (lane & 3) * 2;
#pragma unroll
    for (int mt = 0; mt < 4; mt++) {
        int r0 = m0 + wm * 64 + mt * 16 + cg;
        int r1 = r0 + 8;
#pragma unroll
        for (int nt = 0; nt < 4; nt++) {
            int col = n0 + wn * 32 + nt * 8 + ct;
            float* a4 = acc[mt][nt];
            if (EPI == 0) {
#pragma unroll
                for (int h = 0; h < 2; h++) {
                    int r = h ? r1 : r0;
                    if (r < n_e) {
                        float v0 = a4[h * 2], v1 = a4[h * 2 + 1];
                        float h0 = v0 > 0.f ? v0 * v0 : 0.f;
                        float h1 = v1 > 0.f ? v1 * v1 : 0.f;
                        __half2 hv;
                        hv.x = __float2half_rn(h0);
                        hv.y = __float2half_rn(h1);
                        *(__half2*)(H + (size_t)(base + r) * HDIM + col) = hv;
                    }
                }
            } else {
#pragma unroll
                for (int h = 0; h < 2; h++) {
                    int r = h ? r1 : r0;
                    if (r < n_e) {
                        float w   = g_wt[e * CAP + r];
                        int   gid = g_tok[e * CAP + r];
                        float2 v = make_float2(w * a4[h * 2], w * a4[h * 2 + 1]);
                        *(float2*)(S + (size_t)gid * DIM + col) = v;
                    }
                }
            }
        }
    }
}

// ---------------- combine --------------------------------------------------
__global__ __launch_bounds__(256) void combine_kernel(float* __restrict__ out)
{
    size_t i = (size_t)blockIdx.x * blockDim.x + threadIdx.x;  // float4 index
    const size_t d4 = DIM / 4;
    size_t t = i / d4, c = i % d4;
    const float4* s = (const float4*)P_S;
    float4 p = s[(2 * t) * d4 + c];
    float4 q = s[(2 * t + 1) * d4 + c];
    float4 r2;
    r2.x = p.x + q.x; r2.y = p.y + q.y; r2.z = p.z + q.z; r2.w = p.w + q.w;
    ((float4*)out)[i] = r2;
}

// ---------------- launch ----------------------------------------------------
extern "C" void kernel_launch(void* const* d_in, const int* in_sizes, int n_in,
                              void* d_out, int out_size)
{
    const float* x   = (const float*)d_in[0];   // [4,2048,1024]
    const float* rw  = (const float*)d_in[1];   // [8,1024]
    const float* fc1 = (const float*)d_in[2];   // [8,2048,1024]
    const float* fc2 = (const float*)d_in[3];   // [8,1024,2048]
    float* out = (float*)d_out;

    zero_counts_kernel<<<1, 32>>>();
    router_kernel<<<N_TOK / 8, 256>>>(x, rw);
    scan_kernel<<<1, 32>>>();
    gather_x_kernel<<<dim3(CAP / 8, NEXP), 256>>>(x);
    convert_w_kernel<0><<<(NEXP * HDIM * DIM / 4) / 256, 256>>>(fc1);
    moe_gemm_mma<0><<<dim3(CAP / 128, HDIM / 128, NEXP), 256>>>();
    convert_w_kernel<1><<<(NEXP * DIM * HDIM / 4) / 256, 256>>>(fc2);   // W2 overwrites W1
    moe_gemm_mma<1><<<dim3(CAP / 128, DIM / 128, NEXP), 256>>>();
    combine_kernel<<<(N_TOK * DIM / 4) / 256, 256>>>(out);
}

// round 13
// speedup vs baseline: 7.3436x; 1.0092x over previous
#include <cuda_runtime.h>
#include <cuda_fp16.h>
#include <cstdint>

#define N_TOK 8192
#define DIM   1024
#define NEXP  8
#define HDIM  2048
#define CAP   8192
#define NSLOT (N_TOK * 2)

// ---------------- scratch: single 128MB pool, time-multiplexed -------------
// Phase 1 (gather/convert1/gemm1):  A[0,32) W1[32,64) H[64,128)
// Phase 2 (convert2/gemm2):         W2[32,64) H[64,128)
__device__ __align__(256) unsigned char g_pool[134217728];
#define P_A   ((half*)(g_pool))
#define P_W1  ((half*)(g_pool + (32u << 20)))
#define P_H   ((half*)(g_pool + (64u << 20)))
#define P_W2  ((half*)(g_pool + (32u << 20)))

__device__ int   g_counts[NEXP];
__device__ int   g_base[NEXP];
__device__ int   g_tok[NEXP * CAP];
__device__ float g_wt [NEXP * CAP];

// ---------------- PTX helpers (base sm_100-safe) ---------------------------
__device__ __forceinline__ uint32_t smem_to_u32(const void* p) {
    uint32_t a;
    asm("{ .reg .u64 t; cvta.to.shared.u64 t, %1; cvt.u32.u64 %0, t; }" : "=r"(a) : "l"(p));
    return a;
}
__device__ __forceinline__ void mma_f16(float* c, const uint32_t* a, uint32_t b0, uint32_t b1) {
    asm volatile(
        "mma.sync.aligned.m16n8k16.row.col.f32.f16.f16.f32 "
        "{%0,%1,%2,%3},{%4,%5,%6,%7},{%8,%9},{%0,%1,%2,%3};"
        : "+f"(c[0]), "+f"(c[1]), "+f"(c[2]), "+f"(c[3])
        : "r"(a[0]), "r"(a[1]), "r"(a[2]), "r"(a[3]), "r"(b0), "r"(b1));
}
__device__ __forceinline__ void ldsm4(uint32_t* r, uint32_t addr) {
    asm volatile("ldmatrix.sync.aligned.m8n8.x4.shared.b16 {%0,%1,%2,%3},[%4];"
                 : "=r"(r[0]), "=r"(r[1]), "=r"(r[2]), "=r"(r[3]) : "r"(addr));
}
__device__ __forceinline__ void cpasync16(uint32_t dst, const void* src, int sz) {
    asm volatile("cp.async.cg.shared.global [%0],[%1],16,%2;"
                 :: "r"(dst), "l"(src), "r"(sz) : "memory");
}
#define CP_COMMIT() asm volatile("cp.async.commit_group;" ::: "memory")
#define CP_WAIT(N)  asm volatile("cp.async.wait_group %0;" :: "n"(N) : "memory")

// Swizzled plane: 128 rows x 64B (K-chunk 32 halves).
// addr = row*64 + (byte ^ ((row&6)<<3)) — conflict-free for ldmatrix
// phases (8 rows hit 8 distinct 16B-bank groups) and cp.async stores.
__device__ __forceinline__ uint32_t swz64(int row, int byte) {
    return (uint32_t)(row * 64 + (byte ^ ((row & 6) << 3)));
}

// ---------------- convert helpers ------------------------------------------
__device__ __forceinline__ void cvt4h(float4 v, uint32_t& h01, uint32_t& h23) {
    __half2 H01, H23;
    H01.x = __float2half_rn(v.x); H01.y = __float2half_rn(v.y);
    H23.x = __float2half_rn(v.z); H23.y = __float2half_rn(v.w);
    h01 = *(uint32_t*)&H01; h23 = *(uint32_t*)&H23;
}

// ---------------- prep kernels --------------------------------------------
__global__ void zero_counts_kernel() { if (threadIdx.x < NEXP) g_counts[threadIdx.x] = 0; }

__global__ void scan_kernel() {
    if (threadIdx.x == 0) {
        int acc = 0;
#pragma unroll
        for (int e = 0; e < NEXP; e++) { g_base[e] = acc; acc += g_counts[e]; }
    }
}

__global__ __launch_bounds__(256) void zero_out_kernel(float* __restrict__ out)
{
    size_t i = (size_t)blockIdx.x * 256 + threadIdx.x;
    ((float4*)out)[i] = make_float4(0.f, 0.f, 0.f, 0.f);
}

__global__ __launch_bounds__(256) void router_kernel(
    const float* __restrict__ x, const float* __restrict__ rw)
{
    __shared__ float s_rw[NEXP * DIM];
    int tid = threadIdx.x;
    for (int i = tid; i < NEXP * DIM; i += 256) s_rw[i] = rw[i];
    __syncthreads();

    int warp = tid >> 5, lane = tid & 31;
    int t = blockIdx.x * 8 + warp;
    const float* xr = x + (size_t)t * DIM;

    float acc[NEXP];
#pragma unroll
    for (int e = 0; e < NEXP; e++) acc[e] = 0.0f;
    for (int j = lane; j < DIM; j += 32) {
        float xv = xr[j];
#pragma unroll
        for (int e = 0; e < NEXP; e++) acc[e] += xv * s_rw[e * DIM + j];
    }
#pragma unroll
    for (int e = 0; e < NEXP; e++)
#pragma unroll
        for (int off = 16; off > 0; off >>= 1)
            acc[e] += __shfl_xor_sync(0xFFFFFFFFu, acc[e], off);

    if (lane == 0) {
        int e0 = 0; float l0 = acc[0];
#pragma unroll
        for (int e = 1; e < NEXP; e++) if (acc[e] > l0) { l0 = acc[e]; e0 = e; }
        int e1 = -1; float l1 = -3.0e38f;
#pragma unroll
        for (int e = 0; e < NEXP; e++) if (e != e0 && acc[e] > l1) { l1 = acc[e]; e1 = e; }
        float w0 = 1.0f / (1.0f + expf(l1 - l0));
        float w1 = 1.0f - w0;
        int p0 = atomicAdd(&g_counts[e0], 1);
        g_tok[e0 * CAP + p0] = t;  g_wt[e0 * CAP + p0] = w0;
        int p1 = atomicAdd(&g_counts[e1], 1);
        g_tok[e1 * CAP + p1] = t;  g_wt[e1 * CAP + p1] = w1;
    }
}

__global__ __launch_bounds__(256) void gather_x_kernel(const float* __restrict__ x)
{
    int e = blockIdx.y;
    int i = blockIdx.x * 8 + (threadIdx.x >> 5);
    if (i >= g_counts[e]) return;
    int lane = threadIdx.x & 31;
    int t = g_tok[e * CAP + i];
    size_t dst = (size_t)(g_base[e] + i) * DIM;
    half* A = P_A;
    const float4* src = (const float4*)(x + (size_t)t * DIM);
    for (int c = lane; c < DIM / 4; c += 32) {
        uint32_t h01, h23;
        cvt4h(src[c], h01, h23);
        *(uint2*)(A + dst + c * 4) = make_uint2(h01, h23);
    }
}

template <int W>
__global__ __launch_bounds__(256) void convert_w_kernel(const float* __restrict__ src)
{
    half* dh = W ? P_W2 : P_W1;
    size_t i = (size_t)blockIdx.x * 256 + threadIdx.x;     // float4 index
    float4 v = ((const float4*)src)[i];
    uint32_t h01, h23;
    cvt4h(v, h01, h23);
    *(uint2*)(dh + i * 4) = make_uint2(h01, h23);
}

// ---------------- mma.sync grouped GEMM ------------------------------------
// Block 128x128, 8 warps (2x4), warp tile 64x32, K-chunk 32, 3-stage cp.async,
// STATIC 48KB smem, swizzled 64B-row planes, ONE sync per chunk, 2 CTAs/SM.
// Single-term fp16 MMA (A and B both fp16; fp32 accum).
// GEMM1 (EPI=0): A=fp16(x), B=fp16(fc1) -> relu^2 -> fp16 H.
// GEMM2 (EPI=1): A=H, B=fp16(fc2) -> atomicAdd(w * y) directly into out.
#define PLANE 8192
#define NPL   2
#define NS    3
#define BUF   (NPL * PLANE)

template <int EPI>
__global__ __launch_bounds__(256, 2) void moe_gemm_mma(float* __restrict__ out)
{
    constexpr int KTOT = EPI ? HDIM : DIM;
    constexpr int NTOT = EPI ? DIM : HDIM;
    constexpr int NCH  = KTOT / 32;

    int e   = blockIdx.z;
    int n_e = g_counts[e];
    int m0  = blockIdx.x * 128;
    if (m0 >= n_e) return;
    int base = g_base[e];
    int n0   = blockIdx.y * 128;

    const half* __restrict__ A = EPI ? P_H  : P_A;
    const half* __restrict__ B = EPI ? P_W2 : P_W1;

    __shared__ __align__(16) char smem[NS * BUF];
    uint32_t sb = smem_to_u32(smem);
    int tid = threadIdx.x, wid = tid >> 5, lane = tid & 31;
    int wm = wid >> 2, wn = wid & 3;           // warp grid 2x4

    // ---- copy descriptors: 512 16B-slots per plane; thread t does slots t, t+256
    int row0 = tid >> 2, seg0 = tid & 3;                 // slots 0..255
    int row1 = (tid + 256) >> 2, seg1 = tid & 3;         // slots 256..511
    int gm0 = m0 + row0, gm1 = m0 + row1;
    int av0 = (gm0 < n_e) ? 16 : 0, av1 = (gm1 < n_e) ? 16 : 0;
    size_t aoff0 = (size_t)(base + (av0 ? gm0 : 0)) * KTOT;
    size_t aoff1 = (size_t)(base + (av1 ? gm1 : 0)) * KTOT;
    size_t boff0 = ((size_t)e * NTOT + n0 + row0) * KTOT;
    size_t boff1 = ((size_t)e * NTOT + n0 + row1) * KTOT;
    uint32_t dst0 = sb + swz64(row0, seg0 * 16);
    uint32_t dst1 = sb + swz64(row1, seg1 * 16);

    float acc[4][4][4];
#pragma unroll
    for (int i = 0; i < 4; i++)
#pragma unroll
        for (int j = 0; j < 4; j++)
#pragma unroll
            for (int k = 0; k < 4; k++) acc[i][j][k] = 0.0f;

    auto load_chunk = [&](int c) {
        uint32_t bo = (uint32_t)((c % NS) * BUF);
        size_t k0 = (size_t)c * 32 + seg0 * 8;   // halves
        cpasync16(dst0 + bo,         A + aoff0 + k0, av0);
        cpasync16(dst1 + bo,         A + aoff1 + k0, av1);
        cpasync16(dst0 + bo + PLANE, B + boff0 + k0, 16);
        cpasync16(dst1 + bo + PLANE, B + boff1 + k0, 16);
        CP_COMMIT();
    };

    // ldmatrix lane addressing
    int lt = lane >> 3, lr = lane & 7;
    int a_row = (lt & 1) * 8 + lr, a_kt = (lt >> 1) * 8;   // A tiles: m8 x k8
    int b_n   = (lt >> 1) * 8 + lr, b_kt = (lt & 1) * 8;   // B tiles: n8 x k8

#pragma unroll
    for (int s = 0; s < NS - 1; s++) load_chunk(s);

    for (int c = 0; c < NCH; c++) {
        int rem = NCH - 1 - c;
        if (rem >= 1) CP_WAIT(1); else CP_WAIT(0);
        __syncthreads();
        if (c + NS - 1 < NCH) load_chunk(c + NS - 1);

        uint32_t buf = sb + (uint32_t)((c % NS) * BUF);
#pragma unroll
        for (int ks = 0; ks < 2; ks++) {
            uint32_t ah[4][4], bh[2][4];
#pragma unroll
            for (int mt = 0; mt < 4; mt++) {
                int r = wm * 64 + mt * 16 + a_row;
                ldsm4(ah[mt], buf + swz64(r, ks * 32 + a_kt * 2));
            }
#pragma unroll
            for (int ng = 0; ng < 2; ng++) {
                int r = wn * 32 + ng * 16 + b_n;
                ldsm4(bh[ng], buf + PLANE + swz64(r, ks * 32 + b_kt * 2));
            }
#pragma unroll
            for (int mt = 0; mt < 4; mt++)
#pragma unroll
                for (int nt = 0; nt < 4; nt++) {
                    uint32_t b0 = bh[nt >> 1][(nt & 1) * 2], b1 = bh[nt >> 1][(nt & 1) * 2 + 1];
                    mma_f16(acc[mt][nt], ah[mt], b0, b1);
                }
        }
    }

    // ---- epilogue: c-frag lane l: rows g=l>>2 and g+8, col pair (l&3)*2
    half* H = P_H;
    int cg = lane >> 2, ct = (lane & 3) * 2;
#pragma unroll
    for (int mt = 0; mt < 4; mt++) {
        int r0 = m0 + wm * 64 + mt * 16 + cg;
        int r1 = r0 + 8;
#pragma unroll
        for (int nt = 0; nt < 4; nt++) {
            int col = n0 + wn * 32 + nt * 8 + ct;
            float* a4 = acc[mt][nt];
            if (EPI == 0) {
#pragma unroll
                for (int h = 0; h < 2; h++) {
                    int r = h ? r1 : r0;
                    if (r < n_e) {
                        float v0 = a4[h * 2], v1 = a4[h * 2 + 1];
                        float h0 = v0 > 0.f ? v0 * v0 : 0.f;
                        float h1 = v1 > 0.f ? v1 * v1 : 0.f;
                        __half2 hv;
                        hv.x = __float2half_rn(h0);
                        hv.y = __float2half_rn(h1);
                        *(__half2*)(H + (size_t)(base + r) * HDIM + col) = hv;
                    }
                }
            } else {
#pragma unroll
                for (int h = 0; h < 2; h++) {
                    int r = h ? r1 : r0;
                    if (r < n_e) {
                        float w   = g_wt[e * CAP + r];
                        int   t   = g_tok[e * CAP + r];
                        float* o  = out + (size_t)t * DIM + col;
                        atomicAdd(o,     w * a4[h * 2]);
                        atomicAdd(o + 1, w * a4[h * 2 + 1]);
                    }
                }
            }
        }
    }
}

// ---------------- launch ----------------------------------------------------
extern "C" void kernel_launch(void* const* d_in, const int* in_sizes, int n_in,
                              void* d_out, int out_size)
{
    const float* x   = (const float*)d_in[0];   // [4,2048,1024]
    const float* rw  = (const float*)d_in[1];   // [8,1024]
    const float* fc1 = (const float*)d_in[2];   // [8,2048,1024]
    const float* fc2 = (const float*)d_in[3];   // [8,1024,2048]
    float* out = (float*)d_out;

    zero_counts_kernel<<<1, 32>>>();
    zero_out_kernel<<<(N_TOK * DIM / 4) / 256, 256>>>(out);
    router_kernel<<<N_TOK / 8, 256>>>(x, rw);
    scan_kernel<<<1, 32>>>();
    gather_x_kernel<<<dim3(CAP / 8, NEXP), 256>>>(x);
    convert_w_kernel<0><<<(NEXP * HDIM * DIM / 4) / 256, 256>>>(fc1);
    moe_gemm_mma<0><<<dim3(CAP / 128, HDIM / 128, NEXP), 256>>>(out);
    convert_w_kernel<1><<<(NEXP * DIM * HDIM / 4) / 256, 256>>>(fc2);   // W2 overwrites W1
    moe_gemm_mma<1><<<dim3(CAP / 128, DIM / 128, NEXP), 256>>>(out);
}